// round 13
// baseline (speedup 1.0000x reference)
#include <cuda_runtime.h>
#include <cuda_bf16.h>
#include <mma.h>
#include <cstdint>

using namespace nvcuda;

#define H   12
#define NN  2048
#define DD  128
#define BM  64
#define QG  32          // NN/BM
#define IC  192         // indices_count = 64*round(0.1*2048/64)
#define WHALF 153       // int(0.15*2048)//2
#define SCALE 0.08838834764831843f
#define KSPLIT 3        // kD split factor
#define JSPLIT 2        // kAwm key-range split

// ---------------- scratch (device globals; no allocations allowed) ----------
__device__ float g_P[(size_t)H * NN * NN];   // exp(q.kT * scale), 201 MB
__device__ float g_lp[JSPLIT * H * NN];      // partial rowsums (jh halves)
__device__ float g_bs[H * QG * NN];          // colsum of probs per group
__device__ int   g_idx[(size_t)H * QG * NN]; // selected key indices (compact)
__device__ int   g_cnt[H * QG];
__device__ float g_accD[(size_t)H * QG * KSPLIT * BM * DD];  // kD partials, 38MB
__device__ float g_lsD[H * QG * KSPLIT * BM];

// ---------------- threefry2x32 (JAX-compatible, 20 rounds) ------------------
__host__ __device__ __forceinline__ void tf2x32(uint32_t ka, uint32_t kb,
                                                uint32_t x0, uint32_t x1,
                                                uint32_t& o0, uint32_t& o1) {
    uint32_t ks0 = ka, ks1 = kb, ks2 = ka ^ kb ^ 0x1BD11BDAu;
    x0 += ks0; x1 += ks1;
    const int R0[4] = {13, 15, 26, 6};
    const int R1[4] = {17, 29, 16, 24};
    uint32_t ks[3] = {ks0, ks1, ks2};
#pragma unroll
    for (int g = 0; g < 5; ++g) {
        const int* R = (g & 1) ? R1 : R0;
#pragma unroll
        for (int r = 0; r < 4; ++r) {
            x0 += x1;
            x1 = (x1 << R[r]) | (x1 >> (32 - R[r]));
            x1 ^= x0;
        }
        x0 += ks[(g + 1) % 3];
        x1 += ks[(g + 2) % 3] + (uint32_t)(g + 1);
    }
    o0 = x0; o1 = x1;
}

__device__ __forceinline__ uint32_t tf_fold(uint32_t ka, uint32_t kb,
                                            uint32_t x0, uint32_t x1) {
    uint32_t a, b;
    tf2x32(ka, kb, x0, x1, a, b);
    return a ^ b;   // partitionable 32-bit fold
}

// bf16x2 pack: low 16 bits = x0 (lower element), high 16 bits = x1
__device__ __forceinline__ uint32_t pack_bf16x2(float x0, float x1) {
    uint32_t r;
    asm("cvt.rn.bf16x2.f32 %0, %1, %2;" : "=r"(r) : "f"(x1), "f"(x0));
    return r;
}

// =============================================================================
// kAwm: P = exp(QK^T * scale) via wmma bf16 split-GEMM (hi/lo decomposition)
//       + deterministic PARTIAL row sums -> g_lp[jh]
// grid (it=32, h=12, jh=2), 256 threads (8 warps), ~87.6 KB dyn smem, 2 CTA/SM
// (Measured-good configuration. Do NOT cap registers below natural.)
// =============================================================================

#define ASTR 136   // bf16 elements per A row (128 + 8 pad)
#define BSTR 136   // bf16 elements per B row
#define CSTR 68    // f32 elements per C row (64 + 4 pad)

#define NA64 (64 * ASTR)                 // one 64-row bf16 tile
#define SMEM_AWM (4 * NA64 * 2 + 64 * CSTR * 4 + 512)   // 87552 B

__global__ __launch_bounds__(256, 2) void kAwm(const float* __restrict__ q,
                                               const float* __restrict__ k) {
    extern __shared__ char smemraw[];
    __nv_bfloat16* sAhi = reinterpret_cast<__nv_bfloat16*>(smemraw);
    __nv_bfloat16* sAlo = sAhi + NA64;
    __nv_bfloat16* sBhi = sAlo + NA64;
    __nv_bfloat16* sBlo = sBhi + NA64;
    float* sC = reinterpret_cast<float*>(sBlo + NA64);
    float* sRS = sC + 64 * CSTR;          // 128 floats

    const int t = threadIdx.x;
    const int lane = t & 31;
    const int it = blockIdx.x, h = blockIdx.y, jh = blockIdx.z;
    const int w = t >> 5;
    const int wm = w >> 1;       // 0..3 -> rows wm*16..+15
    const int wn = w & 1;        // 0..1 -> cols wn*32..+31
    const int r16 = lane >> 1;   // 0..15 row within warp tile
    const int ch = (lane & 1) * 16;   // 16-col chunk within warp's 32 cols

    // ---- load Q tile (64 rows x 128 f32) -> bf16 hi/lo ----------------------
    {
        const float2* qg = reinterpret_cast<const float2*>(
            q + ((size_t)h * NN + (size_t)it * 64) * DD);
#pragma unroll
        for (int e = t; e < 64 * 64; e += 256) {
            int r = e >> 6, kp = e & 63;
            float2 x = qg[e];
            uint32_t hp = pack_bf16x2(x.x, x.y);
            float h0 = __uint_as_float(hp << 16);
            float h1 = __uint_as_float(hp & 0xFFFF0000u);
            uint32_t lp = pack_bf16x2(x.x - h0, x.y - h1);
            int off = r * ASTR + 2 * kp;
            *reinterpret_cast<uint32_t*>(sAhi + off) = hp;
            *reinterpret_cast<uint32_t*>(sAlo + off) = lp;
        }
    }

    float rsum = 0.f;
    const int rowbase = h * NN + it * 64;

    const int jt0 = jh * (QG / JSPLIT);
    for (int jtt = 0; jtt < QG / JSPLIT; ++jtt) {
        const int jt = jt0 + jtt;
        __syncthreads();   // all warps done reading previous B before overwrite
        // ---- load K tile (64 keys x 128 dims) -> bf16 hi/lo -----------------
        const float2* kg = reinterpret_cast<const float2*>(
            k + ((size_t)h * NN + (size_t)jt * 64) * DD);
#pragma unroll
        for (int e = t; e < 64 * 64; e += 256) {
            int r = e >> 6, kp = e & 63;
            float2 x = kg[e];
            uint32_t hp = pack_bf16x2(x.x, x.y);
            float h0 = __uint_as_float(hp << 16);
            float h1 = __uint_as_float(hp & 0xFFFF0000u);
            uint32_t lp = pack_bf16x2(x.x - h0, x.y - h1);
            int off = r * BSTR + 2 * kp;
            *reinterpret_cast<uint32_t*>(sBhi + off) = hp;
            *reinterpret_cast<uint32_t*>(sBlo + off) = lp;
        }
        __syncthreads();

        // ---- 3-pass split GEMM into fp32 accumulators -----------------------
        wmma::fragment<wmma::accumulator, 16, 16, 16, float> c0, c1;
        wmma::fill_fragment(c0, 0.f);
        wmma::fill_fragment(c1, 0.f);

        const __nv_bfloat16* Ap[3] = {sAhi, sAhi, sAlo};
        const __nv_bfloat16* Bp[3] = {sBhi, sBlo, sBhi};

#pragma unroll
        for (int p = 0; p < 3; ++p) {
            const __nv_bfloat16* Ab = Ap[p] + (wm * 16) * ASTR;
            const __nv_bfloat16* Bb = Bp[p] + (wn * 32) * BSTR;
#pragma unroll
            for (int kk = 0; kk < 8; ++kk) {
                wmma::fragment<wmma::matrix_a, 16, 16, 16, __nv_bfloat16,
                               wmma::row_major> a0;
                wmma::fragment<wmma::matrix_b, 16, 16, 16, __nv_bfloat16,
                               wmma::col_major> b0, b1;
                wmma::load_matrix_sync(a0, Ab + kk * 16, ASTR);
                wmma::load_matrix_sync(b0, Bb + kk * 16, BSTR);
                wmma::load_matrix_sync(b1, Bb + 16 * BSTR + kk * 16, BSTR);
                wmma::mma_sync(c0, a0, b0, c0);
                wmma::mma_sync(c1, a0, b1, c1);
            }
        }

        // ---- store C (per-warp private region), per-warp epilogue -----------
        float* Cb = sC + (wm * 16) * CSTR + wn * 32;
        wmma::store_matrix_sync(Cb, c0, CSTR, wmma::mem_row_major);
        wmma::store_matrix_sync(Cb + 16, c1, CSTR, wmma::mem_row_major);
        __syncwarp();

        {
            const float* crow = sC + (wm * 16 + r16) * CSTR + wn * 32 + ch;
            float* orow = g_P + (size_t)(rowbase + wm * 16 + r16) * NN
                        + jt * 64 + wn * 32 + ch;
#pragma unroll
            for (int c0i = 0; c0i < 16; c0i += 4) {
                float4 s = *reinterpret_cast<const float4*>(crow + c0i);
                float f0 = __expf(s.x * SCALE);
                float f1 = __expf(s.y * SCALE);
                float f2 = __expf(s.z * SCALE);
                float f3 = __expf(s.w * SCALE);
                rsum += (f0 + f1) + (f2 + f3);
                *reinterpret_cast<float4*>(orow + c0i) =
                    make_float4(f0, f1, f2, f3);
            }
        }
        // top-of-loop __syncthreads orders C reuse (per-warp private anyway)
    }

    // ---- combine row sums: lane pairs -> warp halves -> block ---------------
    rsum += __shfl_xor_sync(0xFFFFFFFFu, rsum, 1);   // both 16-col chunks
    __syncthreads();                                  // sC done, reuse region
    if ((lane & 1) == 0) sRS[wn * 64 + wm * 16 + r16] = rsum;
    __syncthreads();
    if (t < 64)
        g_lp[jh * (H * NN) + rowbase + t] = sRS[t] + sRS[64 + t];
}

// ---------------- kernel B: bs[h][g][j] = sum_i P[i][j]/l_i -----------------
// grid (H*QG, 2), 256 threads, 4 j per thread (float4)
__global__ __launch_bounds__(256) void kB() {
    const int hg = blockIdx.x;
    const int j0 = blockIdx.y * 1024 + threadIdx.x * 4;
    const int h = hg / QG, g = hg % QG;
    __shared__ float sl[BM];
    if (threadIdx.x < BM) {
        int row = h * NN + g * BM + threadIdx.x;
        float l = 0.f;
#pragma unroll
        for (int p = 0; p < JSPLIT; ++p) l += g_lp[p * (H * NN) + row];
        sl[threadIdx.x] = 1.0f / l;
    }
    __syncthreads();
    const float* Pb = g_P + ((size_t)h * NN + (size_t)g * BM) * NN + j0;
    float4 acc = make_float4(0.f, 0.f, 0.f, 0.f);
#pragma unroll 8
    for (int i = 0; i < BM; ++i) {
        float4 x = *reinterpret_cast<const float4*>(Pb + (size_t)i * NN);
        float w = sl[i];
        acc.x += x.x * w; acc.y += x.y * w;
        acc.z += x.z * w; acc.w += x.w * w;
    }
    *reinterpret_cast<float4*>(g_bs + (size_t)hg * NN + j0) = acc;
}

// ---------------- block scan helper -----------------------------------------
__device__ __forceinline__ int blockScanExcl(int val, int t, int* wsum, int& total) {
    __syncthreads();
    int lane = t & 31, w = t >> 5;
    int x = val;
#pragma unroll
    for (int o = 1; o < 32; o <<= 1) {
        int y = __shfl_up_sync(0xFFFFFFFFu, x, o);
        if (lane >= o) x += y;
    }
    if (lane == 31) wsum[w] = x;
    __syncthreads();
    if (t < 8) {
        int y = wsum[t];
#pragma unroll
        for (int o = 1; o < 8; o <<= 1) {
            int z = __shfl_up_sync(0xFFu, y, o);
            if (t >= o) y += z;
        }
        wsum[t] = y;
    }
    __syncthreads();
    int base = (w > 0) ? wsum[w - 1] : 0;
    total = wsum[7];
    return base + x - val;
}

// ---------------- kernel C: top-k select + static + random -> index list ----
__global__ __launch_bounds__(256) void kC(uint32_t k1a, uint32_t k1b,
                                          uint32_t k2a, uint32_t k2b) {
    __shared__ uint32_t su[NN];
    __shared__ int hist[256];
    __shared__ int wsum[8];
    __shared__ int s_digit, s_rem;
    const int hg = blockIdx.x;
    const int g = hg % QG;
    const int t = threadIdx.x;

    const float* bs = g_bs + (size_t)hg * NN;
    for (int e = t; e < NN; e += 256) su[e] = __float_as_uint(bs[e]);
    __syncthreads();

    uint32_t pre = 0, preMask = 0;
    int rem = IC;
    for (int shift = 24; shift >= 0; shift -= 8) {
        hist[t] = 0;
        __syncthreads();
#pragma unroll
        for (int ee = 0; ee < 8; ++ee) {
            uint32_t u = su[t * 8 + ee];
            if ((u & preMask) == pre) atomicAdd(&hist[(u >> shift) & 255], 1);
        }
        __syncthreads();
        if (t == 0) {
            int cum = 0, d = 255;
            for (; d > 0; --d) {
                int c = hist[d];
                if (cum + c >= rem) break;
                cum += c;
            }
            s_digit = d;
            s_rem = rem - cum;
        }
        __syncthreads();
        pre |= ((uint32_t)s_digit) << shift;
        preMask |= 0xFFu << shift;
        rem = s_rem;
        __syncthreads();
    }
    const uint32_t v = pre;
    const int need_eq = rem;

    // rank among equals (ascending index, matching lax.top_k stability)
    int eqc = 0;
#pragma unroll
    for (int ee = 0; ee < 8; ++ee) eqc += (su[t * 8 + ee] == v) ? 1 : 0;
    int dummy;
    int eq_base = blockScanExcl(eqc, t, wsum, dummy);

    const int lo = g * BM + BM / 2 - WHALF;
    const int hi = g * BM + BM / 2 + WHALF;

    unsigned char lf[8];
    int fc = 0, eqrun = eq_base;
#pragma unroll
    for (int ee = 0; ee < 8; ++ee) {
        int j = t * 8 + ee;
        uint32_t u = su[j];
        bool topk = (u > v);
        if (u == v) { topk = topk || (eqrun < need_eq); ++eqrun; }
        bool stat = (j >= lo) && (j < hi);
        uint32_t ilin = (uint32_t)hg * NN + (uint32_t)j;
        uint32_t hb = tf_fold(k1a, k1b, 0u, ilin);
        uint32_t lb = tf_fold(k2a, k2b, 0u, ilin);
        bool rnd = (((hb % 100u) * 96u + (lb % 100u)) % 100u) == 0u;
        bool f = topk || stat || rnd;
        lf[ee] = f ? 1 : 0;
        fc += lf[ee];
    }
    int tot;
    int base = blockScanExcl(fc, t, wsum, tot);
    int* dst = g_idx + (size_t)hg * NN;
    int p = base;
#pragma unroll
    for (int ee = 0; ee < 8; ++ee)
        if (lf[ee]) dst[p++] = t * 8 + ee;
    if (t == 0) g_cnt[hg] = tot;
}

// =============================================================================
// kernel D: sparse PV partials via wmma bf16 split-GEMM (hi/lo on P and V)
// grid (384, KSPLIT), 256 thr (8 warps, 2x4 -> 32x32 warp tiles), 53.5 KB smem
// acc += Ph*Vh + Ph*Vl + Pl*Vh ; ls recomputed from hi+lo (deterministic).
// =============================================================================

#define PSTR 72    // bf16 elements per P row (64 + 8 pad)
#define VSTR 136   // bf16 elements per V row (128 + 8 pad)
#define NPD  (64 * PSTR)   // 4608 bf16
#define NVD  (64 * VSTR)   // 8704 bf16
#define SMEM_KD (NPD * 2 * 2 + NVD * 2 * 2 + 256)   // 53504 B

__global__ __launch_bounds__(256, 3) void kD(const float* __restrict__ vin) {
    extern __shared__ char dsm[];
    __nv_bfloat16* sPhi = reinterpret_cast<__nv_bfloat16*>(dsm);
    __nv_bfloat16* sPlo = sPhi + NPD;
    __nv_bfloat16* sVhi = sPlo + NPD;
    __nv_bfloat16* sVlo = sVhi + NVD;
    int* sIdx = reinterpret_cast<int*>(sVlo + NVD);

    const int hg = blockIdx.x;
    const int s = blockIdx.y;
    const int h = hg / QG;
    const int t = threadIdx.x;
    const int w = t >> 5;
    const int wm = w >> 2;               // 0..1 -> rows wm*32..+31
    const int wn = w & 3;                // 0..3 -> cols wn*32..+31
    int cnt = g_cnt[hg];
    if (cnt < 1) cnt = 1;
    const int* idx = g_idx + (size_t)hg * NN;

    wmma::fragment<wmma::accumulator, 16, 16, 16, float> c00, c01, c10, c11;
    wmma::fill_fragment(c00, 0.f);
    wmma::fill_fragment(c01, 0.f);
    wmma::fill_fragment(c10, 0.f);
    wmma::fill_fragment(c11, 0.f);
    float lsacc = 0.f;

    const float* vb = vin + (size_t)h * NN * DD;
    const size_t prow0 = ((size_t)(hg / QG) * NN + (size_t)(hg % QG) * BM) * NN;

    for (int j0 = s * 64; j0 < cnt; j0 += KSPLIT * 64) {
        const int tl = min(64, cnt - j0);
        __syncthreads();                 // smem free (prev tile fully consumed)
        if (t < 64) sIdx[t] = (t < tl) ? idx[j0 + t] : 0;
        __syncthreads();

        // ---- gather P tile (64 q-rows x 64 keys) -> bf16 hi/lo --------------
#pragma unroll
        for (int e = t; e < 64 * 64; e += 256) {
            int ii = e >> 6, jj = e & 63;
            float v = (jj < tl) ? g_P[prow0 + (size_t)ii * NN + sIdx[jj]] : 0.f;
            __nv_bfloat16 hb = __float2bfloat16(v);
            float hv = __bfloat162float(hb);
            sPhi[ii * PSTR + jj] = hb;
            sPlo[ii * PSTR + jj] = __float2bfloat16(v - hv);
        }
        // ---- gather V tile (64 keys x 128 dims) -> bf16 hi/lo ---------------
#pragma unroll
        for (int e = t; e < 64 * 32; e += 256) {
            int jj = e >> 5, c = e & 31;
            float4 x;
            if (jj < tl) x = reinterpret_cast<const float4*>(vb + (size_t)sIdx[jj] * DD)[c];
            else         x = make_float4(0.f, 0.f, 0.f, 0.f);
            uint32_t h0 = pack_bf16x2(x.x, x.y);
            uint32_t h1 = pack_bf16x2(x.z, x.w);
            float a0 = __uint_as_float(h0 << 16);
            float a1 = __uint_as_float(h0 & 0xFFFF0000u);
            float a2 = __uint_as_float(h1 << 16);
            float a3 = __uint_as_float(h1 & 0xFFFF0000u);
            uint32_t l0 = pack_bf16x2(x.x - a0, x.y - a1);
            uint32_t l1 = pack_bf16x2(x.z - a2, x.w - a3);
            uint32_t* vh = reinterpret_cast<uint32_t*>(sVhi) + (jj * (VSTR / 2) + c * 2);
            uint32_t* vl = reinterpret_cast<uint32_t*>(sVlo) + (jj * (VSTR / 2) + c * 2);
            vh[0] = h0; vh[1] = h1;
            vl[0] = l0; vl[1] = l1;
        }
        __syncthreads();

        // ---- ls: per-row sum of p = hi + lo (deterministic quad reduce) -----
        {
            int row = t >> 2, c0 = (t & 3) * 16;
            const __nv_bfloat16* ph = sPhi + row * PSTR + c0;
            const __nv_bfloat16* pl = sPlo + row * PSTR + c0;
            float sacc = 0.f;
#pragma unroll
            for (int e = 0; e < 16; ++e)
                sacc += __bfloat162float(ph[e]) + __bfloat162float(pl[e]);
            sacc += __shfl_xor_sync(0xFFFFFFFFu, sacc, 1);
            sacc += __shfl_xor_sync(0xFFFFFFFFu, sacc, 2);
            lsacc += sacc;
        }

        // ---- 3-pass split GEMM: acc += Ph*Vh + Ph*Vl + Pl*Vh ----------------
        const __nv_bfloat16* Ap[3] = {sPhi, sPhi, sPlo};
        const __nv_bfloat16* Bp[3] = {sVhi, sVlo, sVhi};
#pragma unroll
        for (int p = 0; p < 3; ++p) {
            const __nv_bfloat16* Ab = Ap[p] + (wm * 32) * PSTR;
            const __nv_bfloat16* Bb = Bp[p] + wn * 32;
#pragma unroll
            for (int kk = 0; kk < 4; ++kk) {
                wmma::fragment<wmma::matrix_a, 16, 16, 16, __nv_bfloat16,
                               wmma::row_major> a0, a1;
                wmma::fragment<wmma::matrix_b, 16, 16, 16, __nv_bfloat16,
                               wmma::row_major> b0, b1;
                wmma::load_matrix_sync(a0, Ab + kk * 16, PSTR);
                wmma::load_matrix_sync(a1, Ab + 16 * PSTR + kk * 16, PSTR);
                wmma::load_matrix_sync(b0, Bb + (kk * 16) * VSTR, VSTR);
                wmma::load_matrix_sync(b1, Bb + (kk * 16) * VSTR + 16, VSTR);
                wmma::mma_sync(c00, a0, b0, c00);
                wmma::mma_sync(c01, a0, b1, c01);
                wmma::mma_sync(c10, a1, b0, c10);
                wmma::mma_sync(c11, a1, b1, c11);
            }
        }
    }

    // ---- write partials straight to global (row-major, ld = DD) -------------
    float* ab = g_accD + ((size_t)hg * KSPLIT + s) * (BM * DD);
    wmma::store_matrix_sync(ab + (wm * 32) * DD + wn * 32,      c00, DD, wmma::mem_row_major);
    wmma::store_matrix_sync(ab + (wm * 32) * DD + wn * 32 + 16, c01, DD, wmma::mem_row_major);
    wmma::store_matrix_sync(ab + (wm * 32 + 16) * DD + wn * 32,      c10, DD, wmma::mem_row_major);
    wmma::store_matrix_sync(ab + (wm * 32 + 16) * DD + wn * 32 + 16, c11, DD, wmma::mem_row_major);
    if ((t & 3) == 0)
        g_lsD[(hg * KSPLIT + s) * BM + (t >> 2)] = lsacc;
}

// ---------------- kernel E: combine kD partials + cache add -----------------
// grid 384, 256 thr. thread t: row = t>>2, 32-dim segment (t&3)*32.
__global__ __launch_bounds__(256) void kE(const float* __restrict__ cache,
                                          float* __restrict__ out) {
    const int hg = blockIdx.x;
    const int h = hg / QG, g = hg % QG;
    const int t = threadIdx.x;
    const int row = t >> 2;
    const int seg = (t & 3) * 32;

    const float* lb = g_lsD + hg * KSPLIT * BM;
    float lsum = 0.f;
#pragma unroll
    for (int s = 0; s < KSPLIT; ++s) lsum += lb[s * BM + row];
    const float inv = 1.0f / lsum;

    const float* ab = g_accD + (size_t)hg * KSPLIT * (BM * DD) + row * DD + seg;
    const size_t grow = (size_t)h * NN + (size_t)g * BM + row;
    const float* cr = cache + grow * DD + seg;
    float* orow = out + grow * DD + seg;

#pragma unroll
    for (int c = 0; c < 32; c += 4) {
        float4 a0 = *reinterpret_cast<const float4*>(ab + c);
        float4 a1 = *reinterpret_cast<const float4*>(ab + BM * DD + c);
        float4 a2 = *reinterpret_cast<const float4*>(ab + 2 * BM * DD + c);
        float4 cv = *reinterpret_cast<const float4*>(cr + c);
        float4 ov;
        ov.x = cv.x + (a0.x + a1.x + a2.x) * inv;
        ov.y = cv.y + (a0.y + a1.y + a2.y) * inv;
        ov.z = cv.z + (a0.z + a1.z + a2.z) * inv;
        ov.w = cv.w + (a0.w + a1.w + a2.w) * inv;
        *reinterpret_cast<float4*>(orow + c) = ov;
    }
}

// ---------------- launch -----------------------------------------------------
extern "C" void kernel_launch(void* const* d_in, const int* in_sizes, int n_in,
                              void* d_out, int out_size) {
    const float* q     = (const float*)d_in[0];
    const float* k     = (const float*)d_in[1];
    const float* v     = (const float*)d_in[2];
    const float* cache = (const float*)d_in[3];
    float* out = (float*)d_out;

    (void)in_sizes; (void)n_in; (void)out_size;

    cudaFuncSetAttribute(kAwm, cudaFuncAttributeMaxDynamicSharedMemorySize, SMEM_AWM);
    cudaFuncSetAttribute(kD, cudaFuncAttributeMaxDynamicSharedMemorySize, SMEM_KD);

    // JAX key(1) = (0,1); partitionable foldlike split -> k1, k2
    uint32_t k1a, k1b, k2a, k2b;
    tf2x32(0u, 1u, 0u, 0u, k1a, k1b);
    tf2x32(0u, 1u, 0u, 1u, k2a, k2b);

    dim3 gA(32, H, JSPLIT);
    kAwm<<<gA, 256, SMEM_AWM>>>(q, k);
    dim3 gB(H * QG, 2);
    kB<<<gB, 256>>>();
    kC<<<H * QG, 256>>>(k1a, k1b, k2a, k2b);
    dim3 gD(H * QG, KSPLIT);
    kD<<<gD, 256, SMEM_KD>>>(v);
    kE<<<H * QG, 256>>>(cache, out);
}

// round 14
// speedup vs baseline: 1.0646x; 1.0646x over previous
#include <cuda_runtime.h>
#include <cuda_bf16.h>
#include <mma.h>
#include <cstdint>

using namespace nvcuda;

#define H   12
#define NN  2048
#define DD  128
#define BM  64
#define QG  32          // NN/BM
#define IC  192         // indices_count = 64*round(0.1*2048/64)
#define WHALF 153       // int(0.15*2048)//2
#define SCALE 0.08838834764831843f
#define KSPLIT 3        // kD split factor
#define JSPLIT 2        // kAwm key-range split

// ---------------- scratch (device globals; no allocations allowed) ----------
__device__ float g_P[(size_t)H * NN * NN];   // exp(q.kT * scale), 201 MB
__device__ float g_lp[JSPLIT * H * NN];      // partial rowsums (jh halves)
__device__ float g_bs[H * QG * NN];          // colsum of probs per group
__device__ int   g_idx[(size_t)H * QG * NN]; // selected key indices (compact)
__device__ int   g_cnt[H * QG];
__device__ float g_accD[(size_t)H * QG * KSPLIT * BM * DD];  // kD partials, 38MB
__device__ float g_lsD[H * QG * KSPLIT * BM];

// ---------------- f32x2 packed math (sm_100+ base ISA) ----------------------
#define FMA_F32X2(d, a, b) \
    asm("fma.rn.f32x2 %0, %1, %2, %0;" : "+l"(d) : "l"(a), "l"(b))
#define ADD_F32X2(d, a) \
    asm("add.rn.f32x2 %0, %0, %1;" : "+l"(d) : "l"(a))
#define PACK_F32X2(d, lo, hi) \
    asm("mov.b64 %0, {%1, %2};" : "=l"(d) : "f"(lo), "f"(hi))
#define UNPACK_F32X2(lo, hi, s) \
    asm("mov.b64 {%0, %1}, %2;" : "=f"(lo), "=f"(hi) : "l"(s))

// ---------------- threefry2x32 (JAX-compatible, 20 rounds) ------------------
__host__ __device__ __forceinline__ void tf2x32(uint32_t ka, uint32_t kb,
                                                uint32_t x0, uint32_t x1,
                                                uint32_t& o0, uint32_t& o1) {
    uint32_t ks0 = ka, ks1 = kb, ks2 = ka ^ kb ^ 0x1BD11BDAu;
    x0 += ks0; x1 += ks1;
    const int R0[4] = {13, 15, 26, 6};
    const int R1[4] = {17, 29, 16, 24};
    uint32_t ks[3] = {ks0, ks1, ks2};
#pragma unroll
    for (int g = 0; g < 5; ++g) {
        const int* R = (g & 1) ? R1 : R0;
#pragma unroll
        for (int r = 0; r < 4; ++r) {
            x0 += x1;
            x1 = (x1 << R[r]) | (x1 >> (32 - R[r]));
            x1 ^= x0;
        }
        x0 += ks[(g + 1) % 3];
        x1 += ks[(g + 2) % 3] + (uint32_t)(g + 1);
    }
    o0 = x0; o1 = x1;
}

__device__ __forceinline__ uint32_t tf_fold(uint32_t ka, uint32_t kb,
                                            uint32_t x0, uint32_t x1) {
    uint32_t a, b;
    tf2x32(ka, kb, x0, x1, a, b);
    return a ^ b;   // partitionable 32-bit fold
}

// bf16x2 pack: low 16 bits = x0 (lower element), high 16 bits = x1
__device__ __forceinline__ uint32_t pack_bf16x2(float x0, float x1) {
    uint32_t r;
    asm("cvt.rn.bf16x2.f32 %0, %1, %2;" : "=r"(r) : "f"(x1), "f"(x0));
    return r;
}

// =============================================================================
// kAwm: P = exp(QK^T * scale) via wmma bf16 split-GEMM (hi/lo decomposition)
//       + deterministic PARTIAL row sums -> g_lp[jh]
// grid (it=32, h=12, jh=2), 256 threads (8 warps), ~87.6 KB dyn smem, 2 CTA/SM
// (Measured-good configuration. Do NOT cap registers below natural.)
// =============================================================================

#define ASTR 136   // bf16 elements per A row (128 + 8 pad)
#define BSTR 136   // bf16 elements per B row
#define CSTR 68    // f32 elements per C row (64 + 4 pad)

#define NA64 (64 * ASTR)                 // one 64-row bf16 tile
#define SMEM_AWM (4 * NA64 * 2 + 64 * CSTR * 4 + 512)   // 87552 B

__global__ __launch_bounds__(256, 2) void kAwm(const float* __restrict__ q,
                                               const float* __restrict__ k) {
    extern __shared__ char smemraw[];
    __nv_bfloat16* sAhi = reinterpret_cast<__nv_bfloat16*>(smemraw);
    __nv_bfloat16* sAlo = sAhi + NA64;
    __nv_bfloat16* sBhi = sAlo + NA64;
    __nv_bfloat16* sBlo = sBhi + NA64;
    float* sC = reinterpret_cast<float*>(sBlo + NA64);
    float* sRS = sC + 64 * CSTR;          // 128 floats

    const int t = threadIdx.x;
    const int lane = t & 31;
    const int it = blockIdx.x, h = blockIdx.y, jh = blockIdx.z;
    const int w = t >> 5;
    const int wm = w >> 1;       // 0..3 -> rows wm*16..+15
    const int wn = w & 1;        // 0..1 -> cols wn*32..+31
    const int r16 = lane >> 1;   // 0..15 row within warp tile
    const int ch = (lane & 1) * 16;   // 16-col chunk within warp's 32 cols

    // ---- load Q tile (64 rows x 128 f32) -> bf16 hi/lo ----------------------
    {
        const float2* qg = reinterpret_cast<const float2*>(
            q + ((size_t)h * NN + (size_t)it * 64) * DD);
#pragma unroll
        for (int e = t; e < 64 * 64; e += 256) {
            int r = e >> 6, kp = e & 63;
            float2 x = qg[e];
            uint32_t hp = pack_bf16x2(x.x, x.y);
            float h0 = __uint_as_float(hp << 16);
            float h1 = __uint_as_float(hp & 0xFFFF0000u);
            uint32_t lp = pack_bf16x2(x.x - h0, x.y - h1);
            int off = r * ASTR + 2 * kp;
            *reinterpret_cast<uint32_t*>(sAhi + off) = hp;
            *reinterpret_cast<uint32_t*>(sAlo + off) = lp;
        }
    }

    float rsum = 0.f;
    const int rowbase = h * NN + it * 64;

    const int jt0 = jh * (QG / JSPLIT);
    for (int jtt = 0; jtt < QG / JSPLIT; ++jtt) {
        const int jt = jt0 + jtt;
        __syncthreads();   // all warps done reading previous B before overwrite
        // ---- load K tile (64 keys x 128 dims) -> bf16 hi/lo -----------------
        const float2* kg = reinterpret_cast<const float2*>(
            k + ((size_t)h * NN + (size_t)jt * 64) * DD);
#pragma unroll
        for (int e = t; e < 64 * 64; e += 256) {
            int r = e >> 6, kp = e & 63;
            float2 x = kg[e];
            uint32_t hp = pack_bf16x2(x.x, x.y);
            float h0 = __uint_as_float(hp << 16);
            float h1 = __uint_as_float(hp & 0xFFFF0000u);
            uint32_t lp = pack_bf16x2(x.x - h0, x.y - h1);
            int off = r * BSTR + 2 * kp;
            *reinterpret_cast<uint32_t*>(sBhi + off) = hp;
            *reinterpret_cast<uint32_t*>(sBlo + off) = lp;
        }
        __syncthreads();

        // ---- 3-pass split GEMM into fp32 accumulators -----------------------
        wmma::fragment<wmma::accumulator, 16, 16, 16, float> c0, c1;
        wmma::fill_fragment(c0, 0.f);
        wmma::fill_fragment(c1, 0.f);

        const __nv_bfloat16* Ap[3] = {sAhi, sAhi, sAlo};
        const __nv_bfloat16* Bp[3] = {sBhi, sBlo, sBhi};

#pragma unroll
        for (int p = 0; p < 3; ++p) {
            const __nv_bfloat16* Ab = Ap[p] + (wm * 16) * ASTR;
            const __nv_bfloat16* Bb = Bp[p] + (wn * 32) * BSTR;
#pragma unroll
            for (int kk = 0; kk < 8; ++kk) {
                wmma::fragment<wmma::matrix_a, 16, 16, 16, __nv_bfloat16,
                               wmma::row_major> a0;
                wmma::fragment<wmma::matrix_b, 16, 16, 16, __nv_bfloat16,
                               wmma::col_major> b0, b1;
                wmma::load_matrix_sync(a0, Ab + kk * 16, ASTR);
                wmma::load_matrix_sync(b0, Bb + kk * 16, BSTR);
                wmma::load_matrix_sync(b1, Bb + 16 * BSTR + kk * 16, BSTR);
                wmma::mma_sync(c0, a0, b0, c0);
                wmma::mma_sync(c1, a0, b1, c1);
            }
        }

        // ---- store C (per-warp private region), per-warp epilogue -----------
        float* Cb = sC + (wm * 16) * CSTR + wn * 32;
        wmma::store_matrix_sync(Cb, c0, CSTR, wmma::mem_row_major);
        wmma::store_matrix_sync(Cb + 16, c1, CSTR, wmma::mem_row_major);
        __syncwarp();

        {
            const float* crow = sC + (wm * 16 + r16) * CSTR + wn * 32 + ch;
            float* orow = g_P + (size_t)(rowbase + wm * 16 + r16) * NN
                        + jt * 64 + wn * 32 + ch;
#pragma unroll
            for (int c0i = 0; c0i < 16; c0i += 4) {
                float4 s = *reinterpret_cast<const float4*>(crow + c0i);
                float f0 = __expf(s.x * SCALE);
                float f1 = __expf(s.y * SCALE);
                float f2 = __expf(s.z * SCALE);
                float f3 = __expf(s.w * SCALE);
                rsum += (f0 + f1) + (f2 + f3);
                *reinterpret_cast<float4*>(orow + c0i) =
                    make_float4(f0, f1, f2, f3);
            }
        }
        // top-of-loop __syncthreads orders C reuse (per-warp private anyway)
    }

    // ---- combine row sums: lane pairs -> warp halves -> block ---------------
    rsum += __shfl_xor_sync(0xFFFFFFFFu, rsum, 1);   // both 16-col chunks
    __syncthreads();                                  // sC done, reuse region
    if ((lane & 1) == 0) sRS[wn * 64 + wm * 16 + r16] = rsum;
    __syncthreads();
    if (t < 64)
        g_lp[jh * (H * NN) + rowbase + t] = sRS[t] + sRS[64 + t];
}

// ---------------- kernel B: bs[h][g][j] = sum_i P[i][j]/l_i -----------------
// grid (H*QG, 2), 256 threads, 4 j per thread (float4)
__global__ __launch_bounds__(256) void kB() {
    const int hg = blockIdx.x;
    const int j0 = blockIdx.y * 1024 + threadIdx.x * 4;
    const int h = hg / QG, g = hg % QG;
    __shared__ float sl[BM];
    if (threadIdx.x < BM) {
        int row = h * NN + g * BM + threadIdx.x;
        float l = 0.f;
#pragma unroll
        for (int p = 0; p < JSPLIT; ++p) l += g_lp[p * (H * NN) + row];
        sl[threadIdx.x] = 1.0f / l;
    }
    __syncthreads();
    const float* Pb = g_P + ((size_t)h * NN + (size_t)g * BM) * NN + j0;
    float4 acc = make_float4(0.f, 0.f, 0.f, 0.f);
#pragma unroll 8
    for (int i = 0; i < BM; ++i) {
        float4 x = *reinterpret_cast<const float4*>(Pb + (size_t)i * NN);
        float w = sl[i];
        acc.x += x.x * w; acc.y += x.y * w;
        acc.z += x.z * w; acc.w += x.w * w;
    }
    *reinterpret_cast<float4*>(g_bs + (size_t)hg * NN + j0) = acc;
}

// ---------------- block scan helper -----------------------------------------
__device__ __forceinline__ int blockScanExcl(int val, int t, int* wsum, int& total) {
    __syncthreads();
    int lane = t & 31, w = t >> 5;
    int x = val;
#pragma unroll
    for (int o = 1; o < 32; o <<= 1) {
        int y = __shfl_up_sync(0xFFFFFFFFu, x, o);
        if (lane >= o) x += y;
    }
    if (lane == 31) wsum[w] = x;
    __syncthreads();
    if (t < 8) {
        int y = wsum[t];
#pragma unroll
        for (int o = 1; o < 8; o <<= 1) {
            int z = __shfl_up_sync(0xFFu, y, o);
            if (t >= o) y += z;
        }
        wsum[t] = y;
    }
    __syncthreads();
    int base = (w > 0) ? wsum[w - 1] : 0;
    total = wsum[7];
    return base + x - val;
}

// ---------------- kernel C: top-k select + static + random -> index list ----
__global__ __launch_bounds__(256) void kC(uint32_t k1a, uint32_t k1b,
                                          uint32_t k2a, uint32_t k2b) {
    __shared__ uint32_t su[NN];
    __shared__ int hist[256];
    __shared__ int wsum[8];
    __shared__ int s_digit, s_rem;
    const int hg = blockIdx.x;
    const int g = hg % QG;
    const int t = threadIdx.x;

    const float* bs = g_bs + (size_t)hg * NN;
    for (int e = t; e < NN; e += 256) su[e] = __float_as_uint(bs[e]);
    __syncthreads();

    uint32_t pre = 0, preMask = 0;
    int rem = IC;
    for (int shift = 24; shift >= 0; shift -= 8) {
        hist[t] = 0;
        __syncthreads();
#pragma unroll
        for (int ee = 0; ee < 8; ++ee) {
            uint32_t u = su[t * 8 + ee];
            if ((u & preMask) == pre) atomicAdd(&hist[(u >> shift) & 255], 1);
        }
        __syncthreads();
        if (t == 0) {
            int cum = 0, d = 255;
            for (; d > 0; --d) {
                int c = hist[d];
                if (cum + c >= rem) break;
                cum += c;
            }
            s_digit = d;
            s_rem = rem - cum;
        }
        __syncthreads();
        pre |= ((uint32_t)s_digit) << shift;
        preMask |= 0xFFu << shift;
        rem = s_rem;
        __syncthreads();
    }
    const uint32_t v = pre;
    const int need_eq = rem;

    // rank among equals (ascending index, matching lax.top_k stability)
    int eqc = 0;
#pragma unroll
    for (int ee = 0; ee < 8; ++ee) eqc += (su[t * 8 + ee] == v) ? 1 : 0;
    int dummy;
    int eq_base = blockScanExcl(eqc, t, wsum, dummy);

    const int lo = g * BM + BM / 2 - WHALF;
    const int hi = g * BM + BM / 2 + WHALF;

    unsigned char lf[8];
    int fc = 0, eqrun = eq_base;
#pragma unroll
    for (int ee = 0; ee < 8; ++ee) {
        int j = t * 8 + ee;
        uint32_t u = su[j];
        bool topk = (u > v);
        if (u == v) { topk = topk || (eqrun < need_eq); ++eqrun; }
        bool stat = (j >= lo) && (j < hi);
        uint32_t ilin = (uint32_t)hg * NN + (uint32_t)j;
        uint32_t hb = tf_fold(k1a, k1b, 0u, ilin);
        uint32_t lb = tf_fold(k2a, k2b, 0u, ilin);
        bool rnd = (((hb % 100u) * 96u + (lb % 100u)) % 100u) == 0u;
        bool f = topk || stat || rnd;
        lf[ee] = f ? 1 : 0;
        fc += lf[ee];
    }
    int tot;
    int base = blockScanExcl(fc, t, wsum, tot);
    int* dst = g_idx + (size_t)hg * NN;
    int p = base;
#pragma unroll
    for (int ee = 0; ee < 8; ++ee)
        if (lf[ee]) dst[p++] = t * 8 + ee;
    if (t == 0) g_cnt[hg] = tot;
}

// =============================================================================
// kernel D: sparse PV partials, scalar gather + packed f32x2 FMA inner loop.
// grid (384, KSPLIT), 256 thr, ~49.9 KB smem, <=64 regs -> 4 CTA/SM.
// P tile stored TRANSPOSED (sPT[jj][row], stride 66) so row-pairs load as b64.
// Accumulators are f32x2 pairs: lane.lo = even row, lane.hi = odd row.
// =============================================================================

#define PTSTR 66   // floats per sPT row (64 rows + 2 pad, even for b64 align)
#define SMEM_KD (64 * 128 * 4 + 64 * PTSTR * 4 + 256)   // 49920 B

__global__ __launch_bounds__(256, 4) void kD(const float* __restrict__ vin) {
    extern __shared__ float dynD[];
    float* sV = dynD;                      // [64 keys][128 dims]
    float* sPT = dynD + 64 * 128;          // [64 keys][64 rows + pad]
    int* sIdx = reinterpret_cast<int*>(dynD + 64 * 128 + 64 * PTSTR);

    const int hg = blockIdx.x;
    const int s = blockIdx.y;
    const int h = hg / QG, g = hg % QG;
    const int t = threadIdx.x;
    const int lane = t & 31;
    const int tg = t >> 5;                 // warp id 0..7 -> rows tg*8..tg*8+7
    int cnt = g_cnt[hg];
    if (cnt < 1) cnt = 1;
    const int* idx = g_idx + (size_t)hg * NN;

    unsigned long long acc[4][4];          // [row-pair][dim] f32x2
#pragma unroll
    for (int rp = 0; rp < 4; ++rp)
#pragma unroll
        for (int d = 0; d < 4; ++d) acc[rp][d] = 0ULL;
    unsigned long long lsp[4] = {0ULL, 0ULL, 0ULL, 0ULL};

    const float* vb = vin + (size_t)h * NN * DD;
    const size_t prow0 = ((size_t)h * NN + (size_t)g * BM) * NN;

    for (int j0 = s * 64; j0 < cnt; j0 += KSPLIT * 64) {
        const int tl = min(64, cnt - j0);
        __syncthreads();
        if (t < 64) sIdx[t] = (t < tl) ? idx[j0 + t] : 0;
        __syncthreads();
        // gather P tile TRANSPOSED: sPT[jj][ii] (zero padded keys)
        for (int e = t; e < 64 * 64; e += 256) {
            int ii = e >> 6, jj = e & 63;
            sPT[jj * PTSTR + ii] =
                (jj < tl) ? g_P[prow0 + (size_t)ii * NN + sIdx[jj]] : 0.f;
        }
        // gather V tile rows
        for (int e = t; e < 64 * 32; e += 256) {
            int jj = e >> 5, c = e & 31;
            float4 val;
            if (jj < tl) val = reinterpret_cast<const float4*>(vb + (size_t)sIdx[jj] * DD)[c];
            else         val = make_float4(0.f, 0.f, 0.f, 0.f);
            reinterpret_cast<float4*>(sV)[jj * 32 + c] = val;
        }
        __syncthreads();

        const float* colbase = sPT + tg * 8;
#pragma unroll 2
        for (int jj = 0; jj < 64; ++jj) {
            float4 v4 = *reinterpret_cast<const float4*>(sV + jj * 128 + lane * 4);
            unsigned long long vx, vy, vz, vw;
            PACK_F32X2(vx, v4.x, v4.x);
            PACK_F32X2(vy, v4.y, v4.y);
            PACK_F32X2(vz, v4.z, v4.z);
            PACK_F32X2(vw, v4.w, v4.w);
            const unsigned long long* col =
                reinterpret_cast<const unsigned long long*>(colbase + jj * PTSTR);
#pragma unroll
            for (int rp = 0; rp < 4; ++rp) {
                unsigned long long pp = col[rp];   // (p_row2rp, p_row2rp+1) bcast
                ADD_F32X2(lsp[rp], pp);
                FMA_F32X2(acc[rp][0], pp, vx);
                FMA_F32X2(acc[rp][1], pp, vy);
                FMA_F32X2(acc[rp][2], pp, vz);
                FMA_F32X2(acc[rp][3], pp, vw);
            }
        }
    }

    // ---- unpack + write partials -------------------------------------------
    float* ab = g_accD + ((size_t)hg * KSPLIT + s) * (BM * DD);
    float* lb = g_lsD + (hg * KSPLIT + s) * BM;
#pragma unroll
    for (int rp = 0; rp < 4; ++rp) {
        float xlo, xhi, ylo, yhi, zlo, zhi, wlo, whi;
        UNPACK_F32X2(xlo, xhi, acc[rp][0]);
        UNPACK_F32X2(ylo, yhi, acc[rp][1]);
        UNPACK_F32X2(zlo, zhi, acc[rp][2]);
        UNPACK_F32X2(wlo, whi, acc[rp][3]);
        int row = tg * 8 + 2 * rp;
        *reinterpret_cast<float4*>(ab + row * DD + lane * 4) =
            make_float4(xlo, ylo, zlo, wlo);
        *reinterpret_cast<float4*>(ab + (row + 1) * DD + lane * 4) =
            make_float4(xhi, yhi, zhi, whi);
        if (lane == 0) {
            float llo, lhi;
            UNPACK_F32X2(llo, lhi, lsp[rp]);
            lb[row] = llo;
            lb[row + 1] = lhi;
        }
    }
}

// ---------------- kernel E: combine kD partials + cache add -----------------
// grid 384, 256 thr. thread t: row = t>>2, 32-dim segment (t&3)*32.
__global__ __launch_bounds__(256) void kE(const float* __restrict__ cache,
                                          float* __restrict__ out) {
    const int hg = blockIdx.x;
    const int h = hg / QG, g = hg % QG;
    const int t = threadIdx.x;
    const int row = t >> 2;
    const int seg = (t & 3) * 32;

    const float* lb = g_lsD + hg * KSPLIT * BM;
    float lsum = 0.f;
#pragma unroll
    for (int s = 0; s < KSPLIT; ++s) lsum += lb[s * BM + row];
    const float inv = 1.0f / lsum;

    const float* ab = g_accD + (size_t)hg * KSPLIT * (BM * DD) + row * DD + seg;
    const size_t grow = (size_t)h * NN + (size_t)g * BM + row;
    const float* cr = cache + grow * DD + seg;
    float* orow = out + grow * DD + seg;

#pragma unroll
    for (int c = 0; c < 32; c += 4) {
        float4 a0 = *reinterpret_cast<const float4*>(ab + c);
        float4 a1 = *reinterpret_cast<const float4*>(ab + BM * DD + c);
        float4 a2 = *reinterpret_cast<const float4*>(ab + 2 * BM * DD + c);
        float4 cv = *reinterpret_cast<const float4*>(cr + c);
        float4 ov;
        ov.x = cv.x + (a0.x + a1.x + a2.x) * inv;
        ov.y = cv.y + (a0.y + a1.y + a2.y) * inv;
        ov.z = cv.z + (a0.z + a1.z + a2.z) * inv;
        ov.w = cv.w + (a0.w + a1.w + a2.w) * inv;
        *reinterpret_cast<float4*>(orow + c) = ov;
    }
}

// ---------------- launch -----------------------------------------------------
extern "C" void kernel_launch(void* const* d_in, const int* in_sizes, int n_in,
                              void* d_out, int out_size) {
    const float* q     = (const float*)d_in[0];
    const float* k     = (const float*)d_in[1];
    const float* v     = (const float*)d_in[2];
    const float* cache = (const float*)d_in[3];
    float* out = (float*)d_out;

    (void)in_sizes; (void)n_in; (void)out_size;

    cudaFuncSetAttribute(kAwm, cudaFuncAttributeMaxDynamicSharedMemorySize, SMEM_AWM);
    cudaFuncSetAttribute(kD, cudaFuncAttributeMaxDynamicSharedMemorySize, SMEM_KD);

    // JAX key(1) = (0,1); partitionable foldlike split -> k1, k2
    uint32_t k1a, k1b, k2a, k2b;
    tf2x32(0u, 1u, 0u, 0u, k1a, k1b);
    tf2x32(0u, 1u, 0u, 1u, k2a, k2b);

    dim3 gA(32, H, JSPLIT);
    kAwm<<<gA, 256, SMEM_AWM>>>(q, k);
    dim3 gB(H * QG, 2);
    kB<<<gB, 256>>>();
    kC<<<H * QG, 256>>>(k1a, k1b, k2a, k2b);
    dim3 gD(H * QG, KSPLIT);
    kD<<<gD, 256, SMEM_KD>>>(v);
    kE<<<H * QG, 256>>>(cache, out);
}

// round 16
// speedup vs baseline: 1.1202x; 1.0523x over previous
#include <cuda_runtime.h>
#include <cuda_bf16.h>
#include <cstdint>

#define H   12
#define NN  2048
#define DD  128
#define BM  64
#define QG  32          // NN/BM
#define IC  192         // indices_count = 64*round(0.1*2048/64)
#define WHALF 153       // int(0.15*2048)//2
#define SCALE 0.08838834764831843f
#define KSPLIT 3        // kD split factor
#define JSPLIT 2        // kAwm key-range split

// ---------------- scratch (device globals; no allocations allowed) ----------
__device__ float g_P[(size_t)H * NN * NN];   // exp(q.kT * scale), 201 MB
__device__ float g_lp[JSPLIT * H * NN];      // partial rowsums (jh halves)
__device__ float g_bs[H * QG * NN];          // colsum of probs per group
__device__ int   g_idx[(size_t)H * QG * NN]; // selected key indices (compact)
__device__ int   g_cnt[H * QG];
__device__ float g_accD[(size_t)H * QG * KSPLIT * BM * DD];  // kD partials, 38MB
__device__ float g_lsD[H * QG * KSPLIT * BM];

// ---------------- f32x2 packed math (sm_100+ base ISA) ----------------------
#define FMA_F32X2(d, a, b) \
    asm("fma.rn.f32x2 %0, %1, %2, %0;" : "+l"(d) : "l"(a), "l"(b))
#define ADD_F32X2(d, a) \
    asm("add.rn.f32x2 %0, %0, %1;" : "+l"(d) : "l"(a))
#define PACK_F32X2(d, lo, hi) \
    asm("mov.b64 %0, {%1, %2};" : "=l"(d) : "f"(lo), "f"(hi))
#define UNPACK_F32X2(lo, hi, s) \
    asm("mov.b64 {%0, %1}, %2;" : "=f"(lo), "=f"(hi) : "l"(s))

// ---------------- smem address helper ----------------------------------------
__device__ __forceinline__ uint32_t smem_u32(const void* p) {
    uint32_t a;
    asm("{ .reg .u64 t; cvta.to.shared.u64 t, %1; cvt.u32.u64 %0, t; }"
        : "=r"(a) : "l"(p));
    return a;
}

// ---------------- threefry2x32 (JAX-compatible, 20 rounds) ------------------
__host__ __device__ __forceinline__ void tf2x32(uint32_t ka, uint32_t kb,
                                                uint32_t x0, uint32_t x1,
                                                uint32_t& o0, uint32_t& o1) {
    uint32_t ks0 = ka, ks1 = kb, ks2 = ka ^ kb ^ 0x1BD11BDAu;
    x0 += ks0; x1 += ks1;
    const int R0[4] = {13, 15, 26, 6};
    const int R1[4] = {17, 29, 16, 24};
    uint32_t ks[3] = {ks0, ks1, ks2};
#pragma unroll
    for (int g = 0; g < 5; ++g) {
        const int* R = (g & 1) ? R1 : R0;
#pragma unroll
        for (int r = 0; r < 4; ++r) {
            x0 += x1;
            x1 = (x1 << R[r]) | (x1 >> (32 - R[r]));
            x1 ^= x0;
        }
        x0 += ks[(g + 1) % 3];
        x1 += ks[(g + 2) % 3] + (uint32_t)(g + 1);
    }
    o0 = x0; o1 = x1;
}

__device__ __forceinline__ uint32_t tf_fold(uint32_t ka, uint32_t kb,
                                            uint32_t x0, uint32_t x1) {
    uint32_t a, b;
    tf2x32(ka, kb, x0, x1, a, b);
    return a ^ b;   // partitionable 32-bit fold
}

// bf16x2 pack: low 16 bits = x0 (lower element), high 16 bits = x1
__device__ __forceinline__ uint32_t pack_bf16x2(float x0, float x1) {
    uint32_t r;
    asm("cvt.rn.bf16x2.f32 %0, %1, %2;" : "=r"(r) : "f"(x1), "f"(x0));
    return r;
}

// =============================================================================
// kAwm: P = exp(QK^T * scale) via raw mma.sync bf16 split-GEMM (hi/lo)
//       + deterministic PARTIAL row sums -> g_lp[jh]
// grid (it=32, h=12, jh=2), 256 threads (8 warps), 68.7 KB dyn smem.
// No C smem tile: epilogue runs on mma accumulator registers directly.
// =============================================================================

#define ASTR 136   // bf16 elements per A row (128 + 8 pad)
#define BSTR 136   // bf16 elements per B row

#define NA64 (64 * ASTR)                      // one 64-row bf16 tile
#define SMEM_AWM (4 * NA64 * 2 + 512)         // 70144 B

__global__ __launch_bounds__(256) void kAwm(const float* __restrict__ q,
                                            const float* __restrict__ k) {
    extern __shared__ char smemraw[];
    __nv_bfloat16* sAhi = reinterpret_cast<__nv_bfloat16*>(smemraw);
    __nv_bfloat16* sAlo = sAhi + NA64;
    __nv_bfloat16* sBhi = sAlo + NA64;
    __nv_bfloat16* sBlo = sBhi + NA64;
    float* sRS = reinterpret_cast<float*>(sBlo + NA64);   // 128 floats

    const int t = threadIdx.x;
    const int lane = t & 31;
    const int it = blockIdx.x, h = blockIdx.y, jh = blockIdx.z;
    const int w = t >> 5;
    const int wm = w >> 1;       // 0..3 -> rows wm*16..+15
    const int wn = w & 1;        // 0..1 -> cols wn*32..+31

    // ---- load Q tile (64 rows x 128 f32) -> bf16 hi/lo ----------------------
    {
        const float2* qg = reinterpret_cast<const float2*>(
            q + ((size_t)h * NN + (size_t)it * 64) * DD);
#pragma unroll
        for (int e = t; e < 64 * 64; e += 256) {
            int r = e >> 6, kp = e & 63;
            float2 x = qg[e];
            uint32_t hp = pack_bf16x2(x.x, x.y);
            float h0 = __uint_as_float(hp << 16);
            float h1 = __uint_as_float(hp & 0xFFFF0000u);
            uint32_t lp = pack_bf16x2(x.x - h0, x.y - h1);
            int off = r * ASTR + 2 * kp;
            *reinterpret_cast<uint32_t*>(sAhi + off) = hp;
            *reinterpret_cast<uint32_t*>(sAlo + off) = lp;
        }
    }

    // ldmatrix lane-offsets (bytes)
    const uint32_t aoff =
        ((uint32_t)(wm * 16 + (lane & 15)) * ASTR + (uint32_t)(lane >> 4) * 8) * 2;
    uint32_t boff[4];
#pragma unroll
    for (int nt = 0; nt < 4; ++nt)
        boff[nt] = ((uint32_t)(wn * 32 + nt * 8 + (lane & 7)) * BSTR
                    + (uint32_t)((lane >> 3) & 1) * 8) * 2;

    const uint32_t aBaseHi = smem_u32(sAhi), aBaseLo = smem_u32(sAlo);
    const uint32_t bBaseHi = smem_u32(sBhi), bBaseLo = smem_u32(sBlo);
    const uint32_t aB3[3] = {aBaseHi, aBaseHi, aBaseLo};
    const uint32_t bB3[3] = {bBaseHi, bBaseLo, bBaseHi};

    float rsumA = 0.f, rsumB = 0.f;       // rows wm*16+l/4 and +8 (this wn half)
    const int rowbase = h * NN + it * 64;
    const int grow0 = rowbase + wm * 16 + (lane >> 2);
    const int colb = wn * 32 + (lane & 3) * 2;

    const int jt0 = jh * (QG / JSPLIT);
    for (int jtt = 0; jtt < QG / JSPLIT; ++jtt) {
        const int jt = jt0 + jtt;
        __syncthreads();   // all warps done reading previous B before overwrite
        // ---- load K tile (64 keys x 128 dims) -> bf16 hi/lo -----------------
        const float2* kg = reinterpret_cast<const float2*>(
            k + ((size_t)h * NN + (size_t)jt * 64) * DD);
#pragma unroll
        for (int e = t; e < 64 * 64; e += 256) {
            int r = e >> 6, kp = e & 63;
            float2 x = kg[e];
            uint32_t hp = pack_bf16x2(x.x, x.y);
            float h0 = __uint_as_float(hp << 16);
            float h1 = __uint_as_float(hp & 0xFFFF0000u);
            uint32_t lp = pack_bf16x2(x.x - h0, x.y - h1);
            int off = r * BSTR + 2 * kp;
            *reinterpret_cast<uint32_t*>(sBhi + off) = hp;
            *reinterpret_cast<uint32_t*>(sBlo + off) = lp;
        }
        __syncthreads();

        // ---- 3-pass split GEMM into register accumulators -------------------
        float c[4][4];
#pragma unroll
        for (int nt = 0; nt < 4; ++nt)
#pragma unroll
            for (int e = 0; e < 4; ++e) c[nt][e] = 0.f;

#pragma unroll
        for (int p = 0; p < 3; ++p) {
            const uint32_t aB = aB3[p] + aoff;
            const uint32_t bB = bB3[p];
#pragma unroll
            for (int kk = 0; kk < 8; ++kk) {
                uint32_t a0, a1, a2, a3;
                asm volatile(
                    "ldmatrix.sync.aligned.m8n8.x4.shared.b16 {%0,%1,%2,%3}, [%4];"
                    : "=r"(a0), "=r"(a1), "=r"(a2), "=r"(a3)
                    : "r"(aB + kk * 32));
#pragma unroll
                for (int nt = 0; nt < 4; ++nt) {
                    uint32_t b0, b1;
                    asm volatile(
                        "ldmatrix.sync.aligned.m8n8.x2.shared.b16 {%0,%1}, [%2];"
                        : "=r"(b0), "=r"(b1)
                        : "r"(bB + boff[nt] + kk * 32));
                    asm volatile(
                        "mma.sync.aligned.m16n8k16.row.col.f32.bf16.bf16.f32 "
                        "{%0,%1,%2,%3}, {%4,%5,%6,%7}, {%8,%9}, {%0,%1,%2,%3};"
                        : "+f"(c[nt][0]), "+f"(c[nt][1]),
                          "+f"(c[nt][2]), "+f"(c[nt][3])
                        : "r"(a0), "r"(a1), "r"(a2), "r"(a3),
                          "r"(b0), "r"(b1));
                }
            }
        }

        // ---- epilogue in registers: exp, partial rowsums, store -------------
#pragma unroll
        for (int nt = 0; nt < 4; ++nt) {
            float f0 = __expf(c[nt][0] * SCALE);
            float f1 = __expf(c[nt][1] * SCALE);
            float f2 = __expf(c[nt][2] * SCALE);
            float f3 = __expf(c[nt][3] * SCALE);
            rsumA += f0 + f1;
            rsumB += f2 + f3;
            int col = jt * 64 + colb + nt * 8;
            *reinterpret_cast<float2*>(g_P + (size_t)grow0 * NN + col) =
                make_float2(f0, f1);
            *reinterpret_cast<float2*>(g_P + (size_t)(grow0 + 8) * NN + col) =
                make_float2(f2, f3);
        }
    }

    // ---- combine row sums: quad -> sRS -> block ------------------------------
    rsumA += __shfl_xor_sync(0xFFFFFFFFu, rsumA, 1);
    rsumA += __shfl_xor_sync(0xFFFFFFFFu, rsumA, 2);
    rsumB += __shfl_xor_sync(0xFFFFFFFFu, rsumB, 1);
    rsumB += __shfl_xor_sync(0xFFFFFFFFu, rsumB, 2);
    __syncthreads();
    if ((lane & 3) == 0) {
        sRS[wn * 64 + wm * 16 + (lane >> 2)] = rsumA;
        sRS[wn * 64 + wm * 16 + 8 + (lane >> 2)] = rsumB;
    }
    __syncthreads();
    if (t < 64)
        g_lp[jh * (H * NN) + rowbase + t] = sRS[t] + sRS[64 + t];
}

// ---------------- kernel B: bs[h][g][j] = sum_i P[i][j]/l_i -----------------
// grid (H*QG, 2), 256 threads, 4 j per thread (float4), MLP 16
__global__ __launch_bounds__(256) void kB() {
    const int hg = blockIdx.x;
    const int j0 = blockIdx.y * 1024 + threadIdx.x * 4;
    const int h = hg / QG, g = hg % QG;
    __shared__ float sl[BM];
    if (threadIdx.x < BM) {
        int row = h * NN + g * BM + threadIdx.x;
        float l = 0.f;
#pragma unroll
        for (int p = 0; p < JSPLIT; ++p) l += g_lp[p * (H * NN) + row];
        sl[threadIdx.x] = 1.0f / l;
    }
    __syncthreads();
    const float* Pb = g_P + ((size_t)h * NN + (size_t)g * BM) * NN + j0;
    float4 acc = make_float4(0.f, 0.f, 0.f, 0.f);
#pragma unroll 16
    for (int i = 0; i < BM; ++i) {
        float4 x = *reinterpret_cast<const float4*>(Pb + (size_t)i * NN);
        float w = sl[i];
        acc.x += x.x * w; acc.y += x.y * w;
        acc.z += x.z * w; acc.w += x.w * w;
    }
    *reinterpret_cast<float4*>(g_bs + (size_t)hg * NN + j0) = acc;
}

// ---------------- block scan helper -----------------------------------------
__device__ __forceinline__ int blockScanExcl(int val, int t, int* wsum, int& total) {
    __syncthreads();
    int lane = t & 31, w = t >> 5;
    int x = val;
#pragma unroll
    for (int o = 1; o < 32; o <<= 1) {
        int y = __shfl_up_sync(0xFFFFFFFFu, x, o);
        if (lane >= o) x += y;
    }
    if (lane == 31) wsum[w] = x;
    __syncthreads();
    if (t < 8) {
        int y = wsum[t];
#pragma unroll
        for (int o = 1; o < 8; o <<= 1) {
            int z = __shfl_up_sync(0xFFu, y, o);
            if (t >= o) y += z;
        }
        wsum[t] = y;
    }
    __syncthreads();
    int base = (w > 0) ? wsum[w - 1] : 0;
    total = wsum[7];
    return base + x - val;
}

// ---------------- kernel C: top-k select + static + random -> index list ----
__global__ __launch_bounds__(256) void kC(uint32_t k1a, uint32_t k1b,
                                          uint32_t k2a, uint32_t k2b) {
    __shared__ uint32_t su[NN];
    __shared__ int hist[256];
    __shared__ int wsum[8];
    __shared__ int s_digit, s_rem;
    const int hg = blockIdx.x;
    const int g = hg % QG;
    const int t = threadIdx.x;

    const float* bs = g_bs + (size_t)hg * NN;
    for (int e = t; e < NN; e += 256) su[e] = __float_as_uint(bs[e]);
    __syncthreads();

    uint32_t pre = 0, preMask = 0;
    int rem = IC;
    for (int shift = 24; shift >= 0; shift -= 8) {
        hist[t] = 0;
        __syncthreads();
#pragma unroll
        for (int ee = 0; ee < 8; ++ee) {
            uint32_t u = su[t * 8 + ee];
            if ((u & preMask) == pre) atomicAdd(&hist[(u >> shift) & 255], 1);
        }
        __syncthreads();
        if (t == 0) {
            int cum = 0, d = 255;
            for (; d > 0; --d) {
                int c = hist[d];
                if (cum + c >= rem) break;
                cum += c;
            }
            s_digit = d;
            s_rem = rem - cum;
        }
        __syncthreads();
        pre |= ((uint32_t)s_digit) << shift;
        preMask |= 0xFFu << shift;
        rem = s_rem;
        __syncthreads();
    }
    const uint32_t v = pre;
    const int need_eq = rem;

    // rank among equals (ascending index, matching lax.top_k stability)
    int eqc = 0;
#pragma unroll
    for (int ee = 0; ee < 8; ++ee) eqc += (su[t * 8 + ee] == v) ? 1 : 0;
    int dummy;
    int eq_base = blockScanExcl(eqc, t, wsum, dummy);

    const int lo = g * BM + BM / 2 - WHALF;
    const int hi = g * BM + BM / 2 + WHALF;

    unsigned char lf[8];
    int fc = 0, eqrun = eq_base;
#pragma unroll
    for (int ee = 0; ee < 8; ++ee) {
        int j = t * 8 + ee;
        uint32_t u = su[j];
        bool topk = (u > v);
        if (u == v) { topk = topk || (eqrun < need_eq); ++eqrun; }
        bool stat = (j >= lo) && (j < hi);
        uint32_t ilin = (uint32_t)hg * NN + (uint32_t)j;
        uint32_t hb = tf_fold(k1a, k1b, 0u, ilin);
        uint32_t lb = tf_fold(k2a, k2b, 0u, ilin);
        bool rnd = (((hb % 100u) * 96u + (lb % 100u)) % 100u) == 0u;
        bool f = topk || stat || rnd;
        lf[ee] = f ? 1 : 0;
        fc += lf[ee];
    }
    int tot;
    int base = blockScanExcl(fc, t, wsum, tot);
    int* dst = g_idx + (size_t)hg * NN;
    int p = base;
#pragma unroll
    for (int ee = 0; ee < 8; ++ee)
        if (lf[ee]) dst[p++] = t * 8 + ee;
    if (t == 0) g_cnt[hg] = tot;
}

// =============================================================================
// kernel D: sparse PV partials, scalar gather + packed f32x2 FMA inner loop.
// grid (384, KSPLIT), 256 thr, ~49.9 KB smem, <=64 regs -> 4 CTA/SM.
// P tile stored TRANSPOSED (sPT[jj][row], stride 66) so row-pairs load as b64.
// Accumulators are f32x2 pairs: lane.lo = even row, lane.hi = odd row.
// =============================================================================

#define PTSTR 66   // floats per sPT row (64 rows + 2 pad, even for b64 align)
#define SMEM_KD (64 * 128 * 4 + 64 * PTSTR * 4 + 256)   // 49920 B

__global__ __launch_bounds__(256, 4) void kD(const float* __restrict__ vin) {
    extern __shared__ float dynD[];
    float* sV = dynD;                      // [64 keys][128 dims]
    float* sPT = dynD + 64 * 128;          // [64 keys][64 rows + pad]
    int* sIdx = reinterpret_cast<int*>(dynD + 64 * 128 + 64 * PTSTR);

    const int hg = blockIdx.x;
    const int s = blockIdx.y;
    const int h = hg / QG, g = hg % QG;
    const int t = threadIdx.x;
    const int lane = t & 31;
    const int tg = t >> 5;                 // warp id 0..7 -> rows tg*8..tg*8+7
    int cnt = g_cnt[hg];
    if (cnt < 1) cnt = 1;
    const int* idx = g_idx + (size_t)hg * NN;

    unsigned long long acc[4][4];          // [row-pair][dim] f32x2
#pragma unroll
    for (int rp = 0; rp < 4; ++rp)
#pragma unroll
        for (int d = 0; d < 4; ++d) acc[rp][d] = 0ULL;
    unsigned long long lsp[4] = {0ULL, 0ULL, 0ULL, 0ULL};

    const float* vb = vin + (size_t)h * NN * DD;
    const size_t prow0 = ((size_t)h * NN + (size_t)g * BM) * NN;

    for (int j0 = s * 64; j0 < cnt; j0 += KSPLIT * 64) {
        const int tl = min(64, cnt - j0);
        __syncthreads();
        if (t < 64) sIdx[t] = (t < tl) ? idx[j0 + t] : 0;
        __syncthreads();
        // gather P tile TRANSPOSED: sPT[jj][ii] (zero padded keys)
        for (int e = t; e < 64 * 64; e += 256) {
            int ii = e >> 6, jj = e & 63;
            sPT[jj * PTSTR + ii] =
                (jj < tl) ? g_P[prow0 + (size_t)ii * NN + sIdx[jj]] : 0.f;
        }
        // gather V tile rows
        for (int e = t; e < 64 * 32; e += 256) {
            int jj = e >> 5, c = e & 31;
            float4 val;
            if (jj < tl) val = reinterpret_cast<const float4*>(vb + (size_t)sIdx[jj] * DD)[c];
            else         val = make_float4(0.f, 0.f, 0.f, 0.f);
            reinterpret_cast<float4*>(sV)[jj * 32 + c] = val;
        }
        __syncthreads();

        const float* colbase = sPT + tg * 8;
#pragma unroll 2
        for (int jj = 0; jj < 64; ++jj) {
            float4 v4 = *reinterpret_cast<const float4*>(sV + jj * 128 + lane * 4);
            unsigned long long vx, vy, vz, vw;
            PACK_F32X2(vx, v4.x, v4.x);
            PACK_F32X2(vy, v4.y, v4.y);
            PACK_F32X2(vz, v4.z, v4.z);
            PACK_F32X2(vw, v4.w, v4.w);
            const unsigned long long* col =
                reinterpret_cast<const unsigned long long*>(colbase + jj * PTSTR);
#pragma unroll
            for (int rp = 0; rp < 4; ++rp) {
                unsigned long long pp = col[rp];   // (p_row2rp, p_row2rp+1) bcast
                ADD_F32X2(lsp[rp], pp);
                FMA_F32X2(acc[rp][0], pp, vx);
                FMA_F32X2(acc[rp][1], pp, vy);
                FMA_F32X2(acc[rp][2], pp, vz);
                FMA_F32X2(acc[rp][3], pp, vw);
            }
        }
    }

    // ---- unpack + write partials -------------------------------------------
    float* ab = g_accD + ((size_t)hg * KSPLIT + s) * (BM * DD);
    float* lb = g_lsD + (hg * KSPLIT + s) * BM;
#pragma unroll
    for (int rp = 0; rp < 4; ++rp) {
        float xlo, xhi, ylo, yhi, zlo, zhi, wlo, whi;
        UNPACK_F32X2(xlo, xhi, acc[rp][0]);
        UNPACK_F32X2(ylo, yhi, acc[rp][1]);
        UNPACK_F32X2(zlo, zhi, acc[rp][2]);
        UNPACK_F32X2(wlo, whi, acc[rp][3]);
        int row = tg * 8 + 2 * rp;
        *reinterpret_cast<float4*>(ab + row * DD + lane * 4) =
            make_float4(xlo, ylo, zlo, wlo);
        *reinterpret_cast<float4*>(ab + (row + 1) * DD + lane * 4) =
            make_float4(xhi, yhi, zhi, whi);
        if (lane == 0) {
            float llo, lhi;
            UNPACK_F32X2(llo, lhi, lsp[rp]);
            lb[row] = llo;
            lb[row + 1] = lhi;
        }
    }
}

// ---------------- kernel E: combine kD partials + cache add -----------------
// grid 384, 256 thr. thread t: row = t>>2, 32-dim segment (t&3)*32.
__global__ __launch_bounds__(256) void kE(const float* __restrict__ cache,
                                          float* __restrict__ out) {
    const int hg = blockIdx.x;
    const int h = hg / QG, g = hg % QG;
    const int t = threadIdx.x;
    const int row = t >> 2;
    const int seg = (t & 3) * 32;

    const float* lb = g_lsD + hg * KSPLIT * BM;
    float lsum = 0.f;
#pragma unroll
    for (int s = 0; s < KSPLIT; ++s) lsum += lb[s * BM + row];
    const float inv = 1.0f / lsum;

    const float* ab = g_accD + (size_t)hg * KSPLIT * (BM * DD) + row * DD + seg;
    const size_t grow = (size_t)h * NN + (size_t)g * BM + row;
    const float* cr = cache + grow * DD + seg;
    float* orow = out + grow * DD + seg;

#pragma unroll
    for (int c = 0; c < 32; c += 4) {
        float4 a0 = *reinterpret_cast<const float4*>(ab + c);
        float4 a1 = *reinterpret_cast<const float4*>(ab + BM * DD + c);
        float4 a2 = *reinterpret_cast<const float4*>(ab + 2 * BM * DD + c);
        float4 cv = *reinterpret_cast<const float4*>(cr + c);
        float4 ov;
        ov.x = cv.x + (a0.x + a1.x + a2.x) * inv;
        ov.y = cv.y + (a0.y + a1.y + a2.y) * inv;
        ov.z = cv.z + (a0.z + a1.z + a2.z) * inv;
        ov.w = cv.w + (a0.w + a1.w + a2.w) * inv;
        *reinterpret_cast<float4*>(orow + c) = ov;
    }
}

// ---------------- launch -----------------------------------------------------
extern "C" void kernel_launch(void* const* d_in, const int* in_sizes, int n_in,
                              void* d_out, int out_size) {
    const float* q     = (const float*)d_in[0];
    const float* k     = (const float*)d_in[1];
    const float* v     = (const float*)d_in[2];
    const float* cache = (const float*)d_in[3];
    float* out = (float*)d_out;

    (void)in_sizes; (void)n_in; (void)out_size;

    cudaFuncSetAttribute(kAwm, cudaFuncAttributeMaxDynamicSharedMemorySize, SMEM_AWM);
    cudaFuncSetAttribute(kD, cudaFuncAttributeMaxDynamicSharedMemorySize, SMEM_KD);

    // JAX key(1) = (0,1); partitionable foldlike split -> k1, k2
    uint32_t k1a, k1b, k2a, k2b;
    tf2x32(0u, 1u, 0u, 0u, k1a, k1b);
    tf2x32(0u, 1u, 0u, 1u, k2a, k2b);

    dim3 gA(32, H, JSPLIT);
    kAwm<<<gA, 256, SMEM_AWM>>>(q, k);
    dim3 gB(H * QG, 2);
    kB<<<gB, 256>>>();
    kC<<<H * QG, 256>>>(k1a, k1b, k2a, k2b);
    dim3 gD(H * QG, KSPLIT);
    kD<<<gD, 256, SMEM_KD>>>(v);
    kE<<<H * QG, 256>>>(cache, out);
}

// round 17
// speedup vs baseline: 1.1788x; 1.0523x over previous
#include <cuda_runtime.h>
#include <cuda_bf16.h>
#include <cstdint>

#define H   12
#define NN  2048
#define DD  128
#define BM  64
#define QG  32          // NN/BM
#define IC  192         // indices_count = 64*round(0.1*2048/64)
#define WHALF 153       // int(0.15*2048)//2
#define SCALE 0.08838834764831843f
#define KSPLIT 3        // kD split factor
#define JSPLIT 2        // kAwm key-range split

// ---------------- scratch (device globals; no allocations allowed) ----------
__device__ float g_P[(size_t)H * NN * NN];   // exp(q.kT * scale), 201 MB
__device__ float g_lp[JSPLIT * H * NN];      // partial rowsums (jh halves)
__device__ float g_bs[H * QG * NN];          // colsum of probs per group
__device__ int   g_idx[(size_t)H * QG * NN]; // selected key indices (compact)
__device__ int   g_cnt[H * QG];
__device__ float g_accD[(size_t)H * QG * KSPLIT * BM * DD];  // kD partials, 38MB
__device__ float g_lsD[H * QG * KSPLIT * BM];
// preconverted K tiles: [h][jt][hi|lo][64 rows][128 bf16] as u32 pairs
__device__ uint32_t g_Kc[H * QG * 2 * 4096];   // 12.6 MB

// ---------------- f32x2 packed math (sm_100+ base ISA) ----------------------
#define FMA_F32X2(d, a, b) \
    asm("fma.rn.f32x2 %0, %1, %2, %0;" : "+l"(d) : "l"(a), "l"(b))
#define ADD_F32X2(d, a) \
    asm("add.rn.f32x2 %0, %0, %1;" : "+l"(d) : "l"(a))
#define PACK_F32X2(d, lo, hi) \
    asm("mov.b64 %0, {%1, %2};" : "=l"(d) : "f"(lo), "f"(hi))
#define UNPACK_F32X2(lo, hi, s) \
    asm("mov.b64 {%0, %1}, %2;" : "=f"(lo), "=f"(hi) : "l"(s))

// ---------------- smem address helper ----------------------------------------
__device__ __forceinline__ uint32_t smem_u32(const void* p) {
    uint32_t a;
    asm("{ .reg .u64 t; cvta.to.shared.u64 t, %1; cvt.u32.u64 %0, t; }"
        : "=r"(a) : "l"(p));
    return a;
}

// ---------------- threefry2x32 (JAX-compatible, 20 rounds) ------------------
__host__ __device__ __forceinline__ void tf2x32(uint32_t ka, uint32_t kb,
                                                uint32_t x0, uint32_t x1,
                                                uint32_t& o0, uint32_t& o1) {
    uint32_t ks0 = ka, ks1 = kb, ks2 = ka ^ kb ^ 0x1BD11BDAu;
    x0 += ks0; x1 += ks1;
    const int R0[4] = {13, 15, 26, 6};
    const int R1[4] = {17, 29, 16, 24};
    uint32_t ks[3] = {ks0, ks1, ks2};
#pragma unroll
    for (int g = 0; g < 5; ++g) {
        const int* R = (g & 1) ? R1 : R0;
#pragma unroll
        for (int r = 0; r < 4; ++r) {
            x0 += x1;
            x1 = (x1 << R[r]) | (x1 >> (32 - R[r]));
            x1 ^= x0;
        }
        x0 += ks[(g + 1) % 3];
        x1 += ks[(g + 2) % 3] + (uint32_t)(g + 1);
    }
    o0 = x0; o1 = x1;
}

__device__ __forceinline__ uint32_t tf_fold(uint32_t ka, uint32_t kb,
                                            uint32_t x0, uint32_t x1) {
    uint32_t a, b;
    tf2x32(ka, kb, x0, x1, a, b);
    return a ^ b;   // partitionable 32-bit fold
}

// bf16x2 pack: low 16 bits = x0 (lower element), high 16 bits = x1
__device__ __forceinline__ uint32_t pack_bf16x2(float x0, float x1) {
    uint32_t r;
    asm("cvt.rn.bf16x2.f32 %0, %1, %2;" : "=r"(r) : "f"(x1), "f"(x0));
    return r;
}

// =============================================================================
// kPre: convert K once -> g_Kc bf16 hi/lo tiles (identical cvt path to before,
// so downstream P is bit-identical). grid (QG, H), 256 threads, ~5 us.
// =============================================================================
__global__ __launch_bounds__(256) void kPre(const float* __restrict__ k) {
    const int jt = blockIdx.x, h = blockIdx.y;
    const int t = threadIdx.x;
    const float2* kg = reinterpret_cast<const float2*>(
        k + ((size_t)h * NN + (size_t)jt * 64) * DD);
    uint32_t* dhi = g_Kc + (size_t)(h * QG + jt) * 2 * 4096;
    uint32_t* dlo = dhi + 4096;
#pragma unroll
    for (int e = t; e < 64 * 64; e += 256) {
        float2 x = kg[e];
        uint32_t hp = pack_bf16x2(x.x, x.y);
        float h0 = __uint_as_float(hp << 16);
        float h1 = __uint_as_float(hp & 0xFFFF0000u);
        uint32_t lp = pack_bf16x2(x.x - h0, x.y - h1);
        dhi[e] = hp;     // row = e>>6, pair = e&63 -> row*64 + pair == e
        dlo[e] = lp;
    }
}

// =============================================================================
// kAwm: P = exp(QK^T * scale) via raw mma.sync bf16 split-GEMM (hi/lo)
//       + deterministic PARTIAL row sums -> g_lp[jh]
// grid (it=32, h=12, jh=2), 256 threads (8 warps), 68.7 KB dyn smem.
// K tiles come preconverted from g_Kc: mainloop load is a pure uint4 copy.
// =============================================================================

#define ASTR 136   // bf16 elements per A row (128 + 8 pad)
#define BSTR 136   // bf16 elements per B row

#define NA64 (64 * ASTR)                      // one 64-row bf16 tile
#define SMEM_AWM (4 * NA64 * 2 + 512)         // 70144 B

__global__ __launch_bounds__(256) void kAwm(const float* __restrict__ q) {
    extern __shared__ char smemraw[];
    __nv_bfloat16* sAhi = reinterpret_cast<__nv_bfloat16*>(smemraw);
    __nv_bfloat16* sAlo = sAhi + NA64;
    __nv_bfloat16* sBhi = sAlo + NA64;
    __nv_bfloat16* sBlo = sBhi + NA64;
    float* sRS = reinterpret_cast<float*>(sBlo + NA64);   // 128 floats

    const int t = threadIdx.x;
    const int lane = t & 31;
    const int it = blockIdx.x, h = blockIdx.y, jh = blockIdx.z;
    const int w = t >> 5;
    const int wm = w >> 1;       // 0..3 -> rows wm*16..+15
    const int wn = w & 1;        // 0..1 -> cols wn*32..+31

    // ---- load Q tile (64 rows x 128 f32) -> bf16 hi/lo ----------------------
    {
        const float2* qg = reinterpret_cast<const float2*>(
            q + ((size_t)h * NN + (size_t)it * 64) * DD);
#pragma unroll
        for (int e = t; e < 64 * 64; e += 256) {
            int r = e >> 6, kp = e & 63;
            float2 x = qg[e];
            uint32_t hp = pack_bf16x2(x.x, x.y);
            float h0 = __uint_as_float(hp << 16);
            float h1 = __uint_as_float(hp & 0xFFFF0000u);
            uint32_t lp = pack_bf16x2(x.x - h0, x.y - h1);
            int off = r * ASTR + 2 * kp;
            *reinterpret_cast<uint32_t*>(sAhi + off) = hp;
            *reinterpret_cast<uint32_t*>(sAlo + off) = lp;
        }
    }

    // ldmatrix lane-offsets (bytes)
    const uint32_t aoff =
        ((uint32_t)(wm * 16 + (lane & 15)) * ASTR + (uint32_t)(lane >> 4) * 8) * 2;
    uint32_t boff[4];
#pragma unroll
    for (int nt = 0; nt < 4; ++nt)
        boff[nt] = ((uint32_t)(wn * 32 + nt * 8 + (lane & 7)) * BSTR
                    + (uint32_t)((lane >> 3) & 1) * 8) * 2;

    const uint32_t aBaseHi = smem_u32(sAhi), aBaseLo = smem_u32(sAlo);
    const uint32_t bBaseHi = smem_u32(sBhi), bBaseLo = smem_u32(sBlo);
    const uint32_t aB3[3] = {aBaseHi, aBaseHi, aBaseLo};
    const uint32_t bB3[3] = {bBaseHi, bBaseLo, bBaseHi};

    float rsumA = 0.f, rsumB = 0.f;       // rows wm*16+l/4 and +8 (this wn half)
    const int rowbase = h * NN + it * 64;
    const int grow0 = rowbase + wm * 16 + (lane >> 2);
    const int colb = wn * 32 + (lane & 3) * 2;

    const int jt0 = jh * (QG / JSPLIT);
    for (int jtt = 0; jtt < QG / JSPLIT; ++jtt) {
        const int jt = jt0 + jtt;
        __syncthreads();   // all warps done reading previous B before overwrite
        // ---- copy preconverted K tile from g_Kc (no conversion math) --------
        {
            const uint4* kt = reinterpret_cast<const uint4*>(
                g_Kc + (size_t)(h * QG + jt) * 2 * 4096);
#pragma unroll
            for (int e = t; e < 1024; e += 256) {
                uint4 vh = kt[e];
                uint4 vl = kt[1024 + e];
                int row = e >> 4, seg = e & 15;     // 16 uint4 per 128-bf16 row
                char* dh = reinterpret_cast<char*>(sBhi) + row * 272 + seg * 16;
                char* dl = reinterpret_cast<char*>(sBlo) + row * 272 + seg * 16;
                *reinterpret_cast<uint2*>(dh) = make_uint2(vh.x, vh.y);
                *reinterpret_cast<uint2*>(dh + 8) = make_uint2(vh.z, vh.w);
                *reinterpret_cast<uint2*>(dl) = make_uint2(vl.x, vl.y);
                *reinterpret_cast<uint2*>(dl + 8) = make_uint2(vl.z, vl.w);
            }
        }
        __syncthreads();

        // ---- 3-pass split GEMM into register accumulators -------------------
        float c[4][4];
#pragma unroll
        for (int nt = 0; nt < 4; ++nt)
#pragma unroll
            for (int e = 0; e < 4; ++e) c[nt][e] = 0.f;

#pragma unroll
        for (int p = 0; p < 3; ++p) {
            const uint32_t aB = aB3[p] + aoff;
            const uint32_t bB = bB3[p];
#pragma unroll
            for (int kk = 0; kk < 8; ++kk) {
                uint32_t a0, a1, a2, a3;
                asm volatile(
                    "ldmatrix.sync.aligned.m8n8.x4.shared.b16 {%0,%1,%2,%3}, [%4];"
                    : "=r"(a0), "=r"(a1), "=r"(a2), "=r"(a3)
                    : "r"(aB + kk * 32));
#pragma unroll
                for (int nt = 0; nt < 4; ++nt) {
                    uint32_t b0, b1;
                    asm volatile(
                        "ldmatrix.sync.aligned.m8n8.x2.shared.b16 {%0,%1}, [%2];"
                        : "=r"(b0), "=r"(b1)
                        : "r"(bB + boff[nt] + kk * 32));
                    asm volatile(
                        "mma.sync.aligned.m16n8k16.row.col.f32.bf16.bf16.f32 "
                        "{%0,%1,%2,%3}, {%4,%5,%6,%7}, {%8,%9}, {%0,%1,%2,%3};"
                        : "+f"(c[nt][0]), "+f"(c[nt][1]),
                          "+f"(c[nt][2]), "+f"(c[nt][3])
                        : "r"(a0), "r"(a1), "r"(a2), "r"(a3),
                          "r"(b0), "r"(b1));
                }
            }
        }

        // ---- epilogue in registers: exp, partial rowsums, store -------------
#pragma unroll
        for (int nt = 0; nt < 4; ++nt) {
            float f0 = __expf(c[nt][0] * SCALE);
            float f1 = __expf(c[nt][1] * SCALE);
            float f2 = __expf(c[nt][2] * SCALE);
            float f3 = __expf(c[nt][3] * SCALE);
            rsumA += f0 + f1;
            rsumB += f2 + f3;
            int col = jt * 64 + colb + nt * 8;
            *reinterpret_cast<float2*>(g_P + (size_t)grow0 * NN + col) =
                make_float2(f0, f1);
            *reinterpret_cast<float2*>(g_P + (size_t)(grow0 + 8) * NN + col) =
                make_float2(f2, f3);
        }
    }

    // ---- combine row sums: quad -> sRS -> block ------------------------------
    rsumA += __shfl_xor_sync(0xFFFFFFFFu, rsumA, 1);
    rsumA += __shfl_xor_sync(0xFFFFFFFFu, rsumA, 2);
    rsumB += __shfl_xor_sync(0xFFFFFFFFu, rsumB, 1);
    rsumB += __shfl_xor_sync(0xFFFFFFFFu, rsumB, 2);
    __syncthreads();
    if ((lane & 3) == 0) {
        sRS[wn * 64 + wm * 16 + (lane >> 2)] = rsumA;
        sRS[wn * 64 + wm * 16 + 8 + (lane >> 2)] = rsumB;
    }
    __syncthreads();
    if (t < 64)
        g_lp[jh * (H * NN) + rowbase + t] = sRS[t] + sRS[64 + t];
}

// ---------------- kernel B: bs[h][g][j] = sum_i P[i][j]/l_i -----------------
// grid (H*QG, 2), 256 threads, 4 j per thread (float4), MLP 16
__global__ __launch_bounds__(256) void kB() {
    const int hg = blockIdx.x;
    const int j0 = blockIdx.y * 1024 + threadIdx.x * 4;
    const int h = hg / QG, g = hg % QG;
    __shared__ float sl[BM];
    if (threadIdx.x < BM) {
        int row = h * NN + g * BM + threadIdx.x;
        float l = 0.f;
#pragma unroll
        for (int p = 0; p < JSPLIT; ++p) l += g_lp[p * (H * NN) + row];
        sl[threadIdx.x] = 1.0f / l;
    }
    __syncthreads();
    const float* Pb = g_P + ((size_t)h * NN + (size_t)g * BM) * NN + j0;
    float4 acc = make_float4(0.f, 0.f, 0.f, 0.f);
#pragma unroll 16
    for (int i = 0; i < BM; ++i) {
        float4 x = *reinterpret_cast<const float4*>(Pb + (size_t)i * NN);
        float w = sl[i];
        acc.x += x.x * w; acc.y += x.y * w;
        acc.z += x.z * w; acc.w += x.w * w;
    }
    *reinterpret_cast<float4*>(g_bs + (size_t)hg * NN + j0) = acc;
}

// ---------------- block scan helper -----------------------------------------
__device__ __forceinline__ int blockScanExcl(int val, int t, int* wsum, int& total) {
    __syncthreads();
    int lane = t & 31, w = t >> 5;
    int x = val;
#pragma unroll
    for (int o = 1; o < 32; o <<= 1) {
        int y = __shfl_up_sync(0xFFFFFFFFu, x, o);
        if (lane >= o) x += y;
    }
    if (lane == 31) wsum[w] = x;
    __syncthreads();
    if (t < 8) {
        int y = wsum[t];
#pragma unroll
        for (int o = 1; o < 8; o <<= 1) {
            int z = __shfl_up_sync(0xFFu, y, o);
            if (t >= o) y += z;
        }
        wsum[t] = y;
    }
    __syncthreads();
    int base = (w > 0) ? wsum[w - 1] : 0;
    total = wsum[7];
    return base + x - val;
}

// ---------------- kernel C: top-k select + static + random -> index list ----
__global__ __launch_bounds__(256) void kC(uint32_t k1a, uint32_t k1b,
                                          uint32_t k2a, uint32_t k2b) {
    __shared__ uint32_t su[NN];
    __shared__ int hist[256];
    __shared__ int wsum[8];
    __shared__ int s_digit, s_rem;
    const int hg = blockIdx.x;
    const int g = hg % QG;
    const int t = threadIdx.x;

    const float* bs = g_bs + (size_t)hg * NN;
    for (int e = t; e < NN; e += 256) su[e] = __float_as_uint(bs[e]);
    __syncthreads();

    uint32_t pre = 0, preMask = 0;
    int rem = IC;
    for (int shift = 24; shift >= 0; shift -= 8) {
        hist[t] = 0;
        __syncthreads();
#pragma unroll
        for (int ee = 0; ee < 8; ++ee) {
            uint32_t u = su[t * 8 + ee];
            if ((u & preMask) == pre) atomicAdd(&hist[(u >> shift) & 255], 1);
        }
        __syncthreads();
        if (t == 0) {
            int cum = 0, d = 255;
            for (; d > 0; --d) {
                int c = hist[d];
                if (cum + c >= rem) break;
                cum += c;
            }
            s_digit = d;
            s_rem = rem - cum;
        }
        __syncthreads();
        pre |= ((uint32_t)s_digit) << shift;
        preMask |= 0xFFu << shift;
        rem = s_rem;
        __syncthreads();
    }
    const uint32_t v = pre;
    const int need_eq = rem;

    // rank among equals (ascending index, matching lax.top_k stability)
    int eqc = 0;
#pragma unroll
    for (int ee = 0; ee < 8; ++ee) eqc += (su[t * 8 + ee] == v) ? 1 : 0;
    int dummy;
    int eq_base = blockScanExcl(eqc, t, wsum, dummy);

    const int lo = g * BM + BM / 2 - WHALF;
    const int hi = g * BM + BM / 2 + WHALF;

    unsigned char lf[8];
    int fc = 0, eqrun = eq_base;
#pragma unroll
    for (int ee = 0; ee < 8; ++ee) {
        int j = t * 8 + ee;
        uint32_t u = su[j];
        bool topk = (u > v);
        if (u == v) { topk = topk || (eqrun < need_eq); ++eqrun; }
        bool stat = (j >= lo) && (j < hi);
        uint32_t ilin = (uint32_t)hg * NN + (uint32_t)j;
        uint32_t hb = tf_fold(k1a, k1b, 0u, ilin);
        uint32_t lb = tf_fold(k2a, k2b, 0u, ilin);
        bool rnd = (((hb % 100u) * 96u + (lb % 100u)) % 100u) == 0u;
        bool f = topk || stat || rnd;
        lf[ee] = f ? 1 : 0;
        fc += lf[ee];
    }
    int tot;
    int base = blockScanExcl(fc, t, wsum, tot);
    int* dst = g_idx + (size_t)hg * NN;
    int p = base;
#pragma unroll
    for (int ee = 0; ee < 8; ++ee)
        if (lf[ee]) dst[p++] = t * 8 + ee;
    if (t == 0) g_cnt[hg] = tot;
}

// =============================================================================
// kernel D: sparse PV partials, scalar gather + packed f32x2 FMA inner loop.
// grid (384, KSPLIT), 256 thr, ~49.9 KB smem, <=64 regs -> 4 CTA/SM.
// P tile stored TRANSPOSED (sPT[jj][row], stride 66) so row-pairs load as b64.
// Accumulators are f32x2 pairs: lane.lo = even row, lane.hi = odd row.
// =============================================================================

#define PTSTR 66   // floats per sPT row (64 rows + 2 pad, even for b64 align)
#define SMEM_KD (64 * 128 * 4 + 64 * PTSTR * 4 + 256)   // 49920 B

__global__ __launch_bounds__(256, 4) void kD(const float* __restrict__ vin) {
    extern __shared__ float dynD[];
    float* sV = dynD;                      // [64 keys][128 dims]
    float* sPT = dynD + 64 * 128;          // [64 keys][64 rows + pad]
    int* sIdx = reinterpret_cast<int*>(dynD + 64 * 128 + 64 * PTSTR);

    const int hg = blockIdx.x;
    const int s = blockIdx.y;
    const int h = hg / QG, g = hg % QG;
    const int t = threadIdx.x;
    const int lane = t & 31;
    const int tg = t >> 5;                 // warp id 0..7 -> rows tg*8..tg*8+7
    int cnt = g_cnt[hg];
    if (cnt < 1) cnt = 1;
    const int* idx = g_idx + (size_t)hg * NN;

    unsigned long long acc[4][4];          // [row-pair][dim] f32x2
#pragma unroll
    for (int rp = 0; rp < 4; ++rp)
#pragma unroll
        for (int d = 0; d < 4; ++d) acc[rp][d] = 0ULL;
    unsigned long long lsp[4] = {0ULL, 0ULL, 0ULL, 0ULL};

    const float* vb = vin + (size_t)h * NN * DD;
    const size_t prow0 = ((size_t)h * NN + (size_t)g * BM) * NN;

    for (int j0 = s * 64; j0 < cnt; j0 += KSPLIT * 64) {
        const int tl = min(64, cnt - j0);
        __syncthreads();
        if (t < 64) sIdx[t] = (t < tl) ? idx[j0 + t] : 0;
        __syncthreads();
        // gather P tile TRANSPOSED: sPT[jj][ii] (zero padded keys)
        for (int e = t; e < 64 * 64; e += 256) {
            int ii = e >> 6, jj = e & 63;
            sPT[jj * PTSTR + ii] =
                (jj < tl) ? g_P[prow0 + (size_t)ii * NN + sIdx[jj]] : 0.f;
        }
        // gather V tile rows
        for (int e = t; e < 64 * 32; e += 256) {
            int jj = e >> 5, c = e & 31;
            float4 val;
            if (jj < tl) val = reinterpret_cast<const float4*>(vb + (size_t)sIdx[jj] * DD)[c];
            else         val = make_float4(0.f, 0.f, 0.f, 0.f);
            reinterpret_cast<float4*>(sV)[jj * 32 + c] = val;
        }
        __syncthreads();

        const float* colbase = sPT + tg * 8;
#pragma unroll 2
        for (int jj = 0; jj < 64; ++jj) {
            float4 v4 = *reinterpret_cast<const float4*>(sV + jj * 128 + lane * 4);
            unsigned long long vx, vy, vz, vw;
            PACK_F32X2(vx, v4.x, v4.x);
            PACK_F32X2(vy, v4.y, v4.y);
            PACK_F32X2(vz, v4.z, v4.z);
            PACK_F32X2(vw, v4.w, v4.w);
            const unsigned long long* col =
                reinterpret_cast<const unsigned long long*>(colbase + jj * PTSTR);
#pragma unroll
            for (int rp = 0; rp < 4; ++rp) {
                unsigned long long pp = col[rp];   // (p_row2rp, p_row2rp+1) bcast
                ADD_F32X2(lsp[rp], pp);
                FMA_F32X2(acc[rp][0], pp, vx);
                FMA_F32X2(acc[rp][1], pp, vy);
                FMA_F32X2(acc[rp][2], pp, vz);
                FMA_F32X2(acc[rp][3], pp, vw);
            }
        }
    }

    // ---- unpack + write partials -------------------------------------------
    float* ab = g_accD + ((size_t)hg * KSPLIT + s) * (BM * DD);
    float* lb = g_lsD + (hg * KSPLIT + s) * BM;
#pragma unroll
    for (int rp = 0; rp < 4; ++rp) {
        float xlo, xhi, ylo, yhi, zlo, zhi, wlo, whi;
        UNPACK_F32X2(xlo, xhi, acc[rp][0]);
        UNPACK_F32X2(ylo, yhi, acc[rp][1]);
        UNPACK_F32X2(zlo, zhi, acc[rp][2]);
        UNPACK_F32X2(wlo, whi, acc[rp][3]);
        int row = tg * 8 + 2 * rp;
        *reinterpret_cast<float4*>(ab + row * DD + lane * 4) =
            make_float4(xlo, ylo, zlo, wlo);
        *reinterpret_cast<float4*>(ab + (row + 1) * DD + lane * 4) =
            make_float4(xhi, yhi, zhi, whi);
        if (lane == 0) {
            float llo, lhi;
            UNPACK_F32X2(llo, lhi, lsp[rp]);
            lb[row] = llo;
            lb[row + 1] = lhi;
        }
    }
}

// ---------------- kernel E: combine kD partials + cache add -----------------
// grid 384, 256 thr. thread t: row = t>>2, 32-dim segment (t&3)*32.
__global__ __launch_bounds__(256) void kE(const float* __restrict__ cache,
                                          float* __restrict__ out) {
    const int hg = blockIdx.x;
    const int h = hg / QG, g = hg % QG;
    const int t = threadIdx.x;
    const int row = t >> 2;
    const int seg = (t & 3) * 32;

    const float* lb = g_lsD + hg * KSPLIT * BM;
    float lsum = 0.f;
#pragma unroll
    for (int s = 0; s < KSPLIT; ++s) lsum += lb[s * BM + row];
    const float inv = 1.0f / lsum;

    const float* ab = g_accD + (size_t)hg * KSPLIT * (BM * DD) + row * DD + seg;
    const size_t grow = (size_t)h * NN + (size_t)g * BM + row;
    const float* cr = cache + grow * DD + seg;
    float* orow = out + grow * DD + seg;

#pragma unroll
    for (int c = 0; c < 32; c += 4) {
        float4 a0 = *reinterpret_cast<const float4*>(ab + c);
        float4 a1 = *reinterpret_cast<const float4*>(ab + BM * DD + c);
        float4 a2 = *reinterpret_cast<const float4*>(ab + 2 * BM * DD + c);
        float4 cv = *reinterpret_cast<const float4*>(cr + c);
        float4 ov;
        ov.x = cv.x + (a0.x + a1.x + a2.x) * inv;
        ov.y = cv.y + (a0.y + a1.y + a2.y) * inv;
        ov.z = cv.z + (a0.z + a1.z + a2.z) * inv;
        ov.w = cv.w + (a0.w + a1.w + a2.w) * inv;
        *reinterpret_cast<float4*>(orow + c) = ov;
    }
}

// ---------------- launch -----------------------------------------------------
extern "C" void kernel_launch(void* const* d_in, const int* in_sizes, int n_in,
                              void* d_out, int out_size) {
    const float* q     = (const float*)d_in[0];
    const float* k     = (const float*)d_in[1];
    const float* v     = (const float*)d_in[2];
    const float* cache = (const float*)d_in[3];
    float* out = (float*)d_out;

    (void)in_sizes; (void)n_in; (void)out_size;

    cudaFuncSetAttribute(kAwm, cudaFuncAttributeMaxDynamicSharedMemorySize, SMEM_AWM);
    cudaFuncSetAttribute(kD, cudaFuncAttributeMaxDynamicSharedMemorySize, SMEM_KD);

    // JAX key(1) = (0,1); partitionable foldlike split -> k1, k2
    uint32_t k1a, k1b, k2a, k2b;
    tf2x32(0u, 1u, 0u, 0u, k1a, k1b);
    tf2x32(0u, 1u, 0u, 1u, k2a, k2b);

    dim3 gP(QG, H);
    kPre<<<gP, 256>>>(k);
    dim3 gA(32, H, JSPLIT);
    kAwm<<<gA, 256, SMEM_AWM>>>(q);
    dim3 gB(H * QG, 2);
    kB<<<gB, 256>>>();
    kC<<<H * QG, 256>>>(k1a, k1b, k2a, k2b);
    dim3 gD(H * QG, KSPLIT);
    kD<<<gD, 256, SMEM_KD>>>(v);
    kE<<<H * QG, 256>>>(cache, out);
}